// round 3
// baseline (speedup 1.0000x reference)
#include <cuda_runtime.h>
#include <math.h>

#define NEGB -1.0e30f

// ----------------- scratch (device globals; allocation-free) -----------------
__device__ float g_pool[268435456];   // 1 GiB, stage-aliased
__device__ float g_pos1[8*2048*3];
__device__ float g_pos2[8*512*3];
__device__ int   g_nidx1[8*2048*64];
__device__ int   g_cnt1[8*2048];
__device__ int   g_nidx2[8*512*64];
__device__ int   g_cnt2[8*512];
__device__ float g_x1[8*2048*128];
__device__ float g_x2cat[8*512*259];
__device__ float g_g1[8*512*256];
__device__ float g_g2[8*512*512];
__device__ float g_g3[8*512*1024];
__device__ float g_gmx[32*1024];
__device__ float g_f1[32*512];
__device__ float g_f2[32*256];
__device__ float g_f3[32*7];

// ----------------- FPS: one block (512 thr) per cloud, points in registers ---
template<int PT>
__global__ void fps_kernel(const float* __restrict__ posIn, float* __restrict__ posOut,
                           int N, int S)
{
    int b = blockIdx.x, t = threadIdx.x;
    int lane = t & 31, warp = t >> 5;
    float px[PT], py[PT], pz[PT], mind[PT];
    const float* p = posIn + (size_t)b*N*3;
    #pragma unroll
    for (int j = 0; j < PT; j++) {
        int i = j*512 + t;
        px[j] = p[3*i]; py[j] = p[3*i+1]; pz[j] = p[3*i+2];
        mind[j] = 3.402823466e38f;
    }
    __shared__ float s_x, s_y, s_z;
    __shared__ float swv[16];
    __shared__ int   swi[16];
    __shared__ int   s_bi;
    if (t == 0) {
        s_x = p[0]; s_y = p[1]; s_z = p[2];
        float* o = posOut + (size_t)b*S*3;
        o[0] = p[0]; o[1] = p[1]; o[2] = p[2];
    }
    __syncthreads();
    for (int s = 1; s < S; s++) {
        float lx = s_x, ly = s_y, lz = s_z;
        float bv = NEGB; int bi = 1 << 30;
        #pragma unroll
        for (int j = 0; j < PT; j++) {
            float dx = __fsub_rn(px[j], lx);
            float dy = __fsub_rn(py[j], ly);
            float dz = __fsub_rn(pz[j], lz);
            float d  = __fadd_rn(__fadd_rn(__fmul_rn(dx,dx), __fmul_rn(dy,dy)), __fmul_rn(dz,dz));
            float m  = fminf(mind[j], d);
            mind[j] = m;
            int gi = j*512 + t;
            if (m > bv || (m == bv && gi < bi)) { bv = m; bi = gi; }
        }
        #pragma unroll
        for (int off = 16; off; off >>= 1) {
            float ov = __shfl_down_sync(0xffffffffu, bv, off);
            int   oi = __shfl_down_sync(0xffffffffu, bi, off);
            if (ov > bv || (ov == bv && oi < bi)) { bv = ov; bi = oi; }
        }
        if (lane == 0) { swv[warp] = bv; swi[warp] = bi; }
        __syncthreads();
        if (t < 32) {
            float v  = (t < 16) ? swv[t] : NEGB;
            int   i2 = (t < 16) ? swi[t] : (1 << 30);
            #pragma unroll
            for (int off = 16; off; off >>= 1) {
                float ov = __shfl_down_sync(0xffffffffu, v, off);
                int   oi = __shfl_down_sync(0xffffffffu, i2, off);
                if (ov > v || (ov == v && oi < i2)) { v = ov; i2 = oi; }
            }
            if (t == 0) s_bi = i2;
        }
        __syncthreads();
        int bidx = s_bi;
        if (t == (bidx & 511)) {
            int j = bidx >> 9;
            s_x = px[j]; s_y = py[j]; s_z = pz[j];
            float* o = posOut + ((size_t)b*S + s)*3;
            o[0] = px[j]; o[1] = py[j]; o[2] = pz[j];
        }
        __syncthreads();
    }
}

// ----------------- radius NN: one warp per query, k=64 -----------------------
__global__ void radius_kernel(const float* __restrict__ posAll, const float* __restrict__ posQ,
                              int N, int M, float r2,
                              int* __restrict__ nidx, int* __restrict__ cnt)
{
    __shared__ unsigned long long cand[8][256];
    __shared__ int scnt[8];
    int warp = threadIdx.x >> 5, lane = threadIdx.x & 31;
    int q = blockIdx.x * 8 + warp;
    int b = q / M;
    if (lane == 0) scnt[warp] = 0;
    __syncwarp();
    const float* qp = posQ + (size_t)q*3;
    float qx = qp[0], qy = qp[1], qz = qp[2];
    const float* p = posAll + (size_t)b*N*3;
    for (int i = lane; i < N; i += 32) {
        float dx = __fsub_rn(qx, p[3*i]);
        float dy = __fsub_rn(qy, p[3*i+1]);
        float dz = __fsub_rn(qz, p[3*i+2]);
        float d2 = __fadd_rn(__fadd_rn(__fmul_rn(dx,dx), __fmul_rn(dy,dy)), __fmul_rn(dz,dz));
        if (d2 <= r2) {
            int pos = atomicAdd(&scnt[warp], 1);
            if (pos < 256)
                cand[warp][pos] = ((unsigned long long)__float_as_uint(d2) << 32) | (unsigned)i;
        }
    }
    __syncwarp();
    int c = scnt[warp]; if (c > 256) c = 256;
    int* out = nidx + (size_t)q*64;
    if (c <= 64) {
        for (int t = lane; t < c; t += 32) out[t] = (int)(cand[warp][t] & 0xffffffffu);
        if (lane == 0) cnt[q] = c;
    } else {
        int slots = (c + 31) >> 5;
        for (int sel = 0; sel < 64; sel++) {
            unsigned long long best = ~0ULL;
            for (int k = 0; k < slots; k++) {
                int j = lane + (k << 5);
                if (j < c) { unsigned long long v = cand[warp][j]; if (v < best) best = v; }
            }
            #pragma unroll
            for (int off = 16; off; off >>= 1) {
                unsigned long long o = __shfl_down_sync(0xffffffffu, best, off);
                if (o < best) best = o;
            }
            best = __shfl_sync(0xffffffffu, best, 0);
            if (lane == 0) out[sel] = (int)(best & 0xffffffffu);
            for (int k = 0; k < slots; k++) {
                int j = lane + (k << 5);
                if (j < c && cand[warp][j] == best) cand[warp][j] = ~0ULL;
            }
        }
        if (lane == 0) cnt[q] = 64;
    }
}

// ----------------- stage-1 fused gather + layer1 (3->64, relu) ---------------
__global__ void gf1_kernel(const float* __restrict__ pts,
                           const float* __restrict__ w1, const float* __restrict__ b1,
                           float* __restrict__ h1)
{
    int m = blockIdx.x * 8 + (threadIdx.x >> 5);   // message id, < 1048576
    int lane = threadIdx.x & 31;
    int q = m >> 6, n = m & 63, b = q >> 11;
    int c = g_cnt1[q];
    int idx = (n < c) ? g_nidx1[m] : 0;
    const float* sp = pts + ((size_t)b*4096 + idx)*3;
    const float* qp = g_pos1 + (size_t)q*3;
    float rx = __fsub_rn(sp[0], qp[0]);
    float ry = __fsub_rn(sp[1], qp[1]);
    float rz = __fsub_rn(sp[2], qp[2]);
    float* dst = h1 + (size_t)m*64;
    #pragma unroll
    for (int k = 0; k < 2; k++) {
        int j = lane + k*32;
        float v = fmaf(rz, w1[128+j], fmaf(ry, w1[64+j], fmaf(rx, w1[j], b1[j])));
        dst[j] = fmaxf(v, 0.f);
    }
}

// ----------------- stage-2 gather: msg2[m] = [x1[nidx], rel] -----------------
__global__ void gather2_kernel(const float* __restrict__ x1, float* __restrict__ msg2)
{
    int m = blockIdx.x * 8 + (threadIdx.x >> 5);   // < 262144
    int lane = threadIdx.x & 31;
    int q = m >> 6, n = m & 63, b = q >> 9;
    int c = g_cnt2[q];
    int idx = (n < c) ? g_nidx2[m] : 0;
    const float* src = x1 + ((size_t)b*2048 + idx)*128;
    float* dst = msg2 + (size_t)m*131;
    #pragma unroll
    for (int k = 0; k < 4; k++) dst[lane + k*32] = src[lane + k*32];
    if (lane < 3)
        dst[128+lane] = __fsub_rn(g_pos1[((size_t)b*2048 + idx)*3 + lane],
                                  g_pos2[(size_t)q*3 + lane]);
}

// ----------------- generic tiled GEMM: C[M,N] = A[M,K] @ W[K,N] + b ----------
__global__ void gemm_k(const float* __restrict__ A, const float* __restrict__ W,
                       const float* __restrict__ bias, float* __restrict__ C,
                       int M, int N, int K, int relu)
{
    __shared__ float As[16][132];
    __shared__ float Bs[16][64];
    int tid = threadIdx.x;
    int tr = tid >> 4, tc = tid & 15;
    int row0 = blockIdx.y * 128, col0 = blockIdx.x * 64;
    float acc[8][4];
    #pragma unroll
    for (int i = 0; i < 8; i++)
        #pragma unroll
        for (int j = 0; j < 4; j++) acc[i][j] = 0.f;
    for (int k0 = 0; k0 < K; k0 += 16) {
        #pragma unroll
        for (int l = 0; l < 8; l++) {
            int i = tid + l*256, r = i >> 4, c = i & 15;
            int gr = row0 + r, gc = k0 + c;
            As[c][r] = (gr < M && gc < K) ? A[(size_t)gr*K + gc] : 0.f;
        }
        #pragma unroll
        for (int l = 0; l < 4; l++) {
            int i = tid + l*256, r = i >> 6, c = i & 63;
            int gr = k0 + r, gc = col0 + c;
            Bs[r][c] = (gr < K && gc < N) ? W[(size_t)gr*N + gc] : 0.f;
        }
        __syncthreads();
        #pragma unroll
        for (int k = 0; k < 16; k++) {
            float a[8], bb[4];
            #pragma unroll
            for (int i = 0; i < 8; i++) a[i] = As[k][tr*8 + i];
            #pragma unroll
            for (int j = 0; j < 4; j++) bb[j] = Bs[k][tc*4 + j];
            #pragma unroll
            for (int i = 0; i < 8; i++)
                #pragma unroll
                for (int j = 0; j < 4; j++) acc[i][j] = fmaf(a[i], bb[j], acc[i][j]);
        }
        __syncthreads();
    }
    #pragma unroll
    for (int i = 0; i < 8; i++) {
        int gr = row0 + tr*8 + i;
        if (gr < M) {
            #pragma unroll
            for (int j = 0; j < 4; j++) {
                int gc = col0 + tc*4 + j;
                if (gc < N) {
                    float v = acc[i][j] + bias[gc];
                    if (relu) v = fmaxf(v, 0.f);
                    C[(size_t)gr*N + gc] = v;
                }
            }
        }
    }
}

// ----------------- masked max over k=64 neighbors + relu ---------------------
__global__ void maxagg_kernel(const float* __restrict__ h, const int* __restrict__ cnt,
                              float* __restrict__ out, int C, int ostride)
{
    int q = blockIdx.x, j = threadIdx.x;
    int c = cnt[q];
    const float* base = h + (size_t)q*64*C + j;
    float m = NEGB;
    for (int n = 0; n < c; n++) m = fmaxf(m, base[(size_t)n*C]);
    out[(size_t)q*ostride + j] = fmaxf(m, 0.f);   // relu; 0 if no valid
}

// ----------------- write pos2 into x2cat cols 256..258 -----------------------
__global__ void poscat_kernel()
{
    int t = blockIdx.x * 256 + threadIdx.x;
    if (t < 4096*3) {
        int q = t / 3, c = t % 3;
        g_x2cat[(size_t)q*259 + 256 + c] = g_pos2[t];
    }
}

// ----------------- group max: [4096,1024] -> [32,1024] (groups of 128) -------
__global__ void gmax_kernel()
{
    int j = blockIdx.x * 256 + threadIdx.x;
    int g = blockIdx.y;
    float m = NEGB;
    const float* base = g_g3 + (size_t)g*128*1024 + j;
    for (int i = 0; i < 128; i++) m = fmaxf(m, base[(size_t)i*1024]);
    g_gmx[(size_t)g*1024 + j] = m;
}

// ----------------- final: mean over 4 groups + quat normalize ----------------
__global__ void final_kernel(float* __restrict__ out)
{
    __shared__ float sm[8][7];
    int t = threadIdx.x;
    if (t < 56) {
        int b = t / 7, c = t % 7;
        float s = g_f3[(b*4)*7+c] + g_f3[(b*4+1)*7+c] + g_f3[(b*4+2)*7+c] + g_f3[(b*4+3)*7+c];
        sm[b][c] = s * 0.25f;
    }
    __syncthreads();
    if (t < 8) {
        float q0 = sm[t][3], q1 = sm[t][4], q2 = sm[t][5], q3 = sm[t][6];
        float nrm = sqrtf(q0*q0 + q1*q1 + q2*q2 + q3*q3);
        float d = fmaxf(nrm, 1e-12f);
        out[t*7+0] = sm[t][0]; out[t*7+1] = sm[t][1]; out[t*7+2] = sm[t][2];
        out[t*7+3] = q0/d; out[t*7+4] = q1/d; out[t*7+5] = q2/d; out[t*7+6] = q3/d;
    }
}

// ----------------- launcher --------------------------------------------------
extern "C" void kernel_launch(void* const* d_in, const int* in_sizes, int n_in,
                              void* d_out, int out_size)
{
    const float* pts  = (const float*)d_in[0];
    const float *s1w1 = (const float*)d_in[1],  *s1b1 = (const float*)d_in[2];
    const float *s1w2 = (const float*)d_in[3],  *s1b2 = (const float*)d_in[4];
    const float *s1w3 = (const float*)d_in[5],  *s1b3 = (const float*)d_in[6];
    const float *s2w1 = (const float*)d_in[7],  *s2b1 = (const float*)d_in[8];
    const float *s2w2 = (const float*)d_in[9],  *s2b2 = (const float*)d_in[10];
    const float *s2w3 = (const float*)d_in[11], *s2b3 = (const float*)d_in[12];
    const float *gw1  = (const float*)d_in[13], *gb1  = (const float*)d_in[14];
    const float *gw2  = (const float*)d_in[15], *gb2  = (const float*)d_in[16];
    const float *gw3  = (const float*)d_in[17], *gb3  = (const float*)d_in[18];
    const float *l1w  = (const float*)d_in[19], *l1b  = (const float*)d_in[20];
    const float *l2w  = (const float*)d_in[21], *l2b  = (const float*)d_in[22];
    const float *l3w  = (const float*)d_in[23], *l3b  = (const float*)d_in[24];

    float *pool, *pos1, *pos2, *x1, *x2cat, *g1b, *g2b, *g3b, *gmx, *f1, *f2, *f3;
    int *nidx1, *cnt1, *nidx2, *cnt2;
    cudaGetSymbolAddress((void**)&pool,  g_pool);
    cudaGetSymbolAddress((void**)&pos1,  g_pos1);
    cudaGetSymbolAddress((void**)&pos2,  g_pos2);
    cudaGetSymbolAddress((void**)&nidx1, g_nidx1);
    cudaGetSymbolAddress((void**)&cnt1,  g_cnt1);
    cudaGetSymbolAddress((void**)&nidx2, g_nidx2);
    cudaGetSymbolAddress((void**)&cnt2,  g_cnt2);
    cudaGetSymbolAddress((void**)&x1,    g_x1);
    cudaGetSymbolAddress((void**)&x2cat, g_x2cat);
    cudaGetSymbolAddress((void**)&g1b,   g_g1);
    cudaGetSymbolAddress((void**)&g2b,   g_g2);
    cudaGetSymbolAddress((void**)&g3b,   g_g3);
    cudaGetSymbolAddress((void**)&gmx,   g_gmx);
    cudaGetSymbolAddress((void**)&f1,    g_f1);
    cudaGetSymbolAddress((void**)&f2,    g_f2);
    cudaGetSymbolAddress((void**)&f3,    g_f3);

    // stage-aliased pool views
    float* h1s1 = pool;                  // 1048576 x 64
    float* h2s1 = pool + 67108864;       // 1048576 x 64
    float* h3s1 = pool + 134217728;      // 1048576 x 128
    float* msg2 = pool;                  // 262144 x 131
    float* h1s2 = pool + 34340864;       // 262144 x 128
    float* h2s2 = pool + 67895296;       // 262144 x 128
    float* h3s2 = pool + 101449728;      // 262144 x 256

    float r2a = (float)(0.1*0.1), r2b = (float)(0.2*0.2);

    // ---- stage 1 ----
    fps_kernel<8><<<8, 512>>>(pts, pos1, 4096, 2048);
    radius_kernel<<<2048, 256>>>(pts, pos1, 4096, 2048, r2a, nidx1, cnt1);
    gf1_kernel<<<131072, 256>>>(pts, s1w1, s1b1, h1s1);
    gemm_k<<<dim3(1, 8192), 256>>>(h1s1, s1w2, s1b2, h2s1, 1048576, 64, 64, 1);
    gemm_k<<<dim3(2, 8192), 256>>>(h2s1, s1w3, s1b3, h3s1, 1048576, 128, 64, 0);
    maxagg_kernel<<<16384, 128>>>(h3s1, cnt1, x1, 128, 128);

    // ---- stage 2 ----
    fps_kernel<4><<<8, 512>>>(pos1, pos2, 2048, 512);
    radius_kernel<<<512, 256>>>(pos1, pos2, 2048, 512, r2b, nidx2, cnt2);
    gather2_kernel<<<32768, 256>>>(x1, msg2);
    gemm_k<<<dim3(2, 2048), 256>>>(msg2, s2w1, s2b1, h1s2, 262144, 128, 131, 1);
    gemm_k<<<dim3(2, 2048), 256>>>(h1s2, s2w2, s2b2, h2s2, 262144, 128, 128, 1);
    gemm_k<<<dim3(4, 2048), 256>>>(h2s2, s2w3, s2b3, h3s2, 262144, 256, 128, 0);
    maxagg_kernel<<<4096, 256>>>(h3s2, cnt2, x2cat, 256, 259);
    poscat_kernel<<<48, 256>>>();

    // ---- global MLP + pooling + head ----
    gemm_k<<<dim3(4, 32), 256>>>(x2cat, gw1, gb1, g1b, 4096, 256, 259, 1);
    gemm_k<<<dim3(8, 32), 256>>>(g1b, gw2, gb2, g2b, 4096, 512, 256, 1);
    gemm_k<<<dim3(16, 32), 256>>>(g2b, gw3, gb3, g3b, 4096, 1024, 512, 0);
    gmax_kernel<<<dim3(4, 32), 256>>>();
    gemm_k<<<dim3(8, 1), 256>>>(gmx, l1w, l1b, f1, 32, 512, 1024, 1);
    gemm_k<<<dim3(4, 1), 256>>>(f1, l2w, l2b, f2, 32, 256, 512, 1);
    gemm_k<<<dim3(1, 1), 256>>>(f2, l3w, l3b, f3, 32, 7, 256, 0);
    final_kernel<<<1, 64>>>((float*)d_out);
}

// round 4
// speedup vs baseline: 1.0859x; 1.0859x over previous
#include <cuda_runtime.h>
#include <math.h>

#define NEGB -1.0e30f

// ----------------- scratch -----------------
__device__ float g_pool[67108864];    // h2 stage-2 (262144x128) and spare
__device__ float g_pos1[8*2048*3];
__device__ float g_pos2[8*512*3];
__device__ int   g_nidx1[8*2048*64];
__device__ int   g_cnt1[8*2048];
__device__ int   g_nidx2[8*512*64];
__device__ int   g_cnt2[8*512];
__device__ float g_x1[8*2048*128];
__device__ float g_x2cat[8*512*259];
__device__ float g_g1[8*512*256];
__device__ float g_g2[8*512*512];
__device__ float g_g3[8*512*1024];
__device__ float g_gmx[32*1024];
__device__ float g_f1[32*512];
__device__ float g_f2[32*256];
__device__ float g_f3[32*7];

// ----------------- FPS (unchanged, exact) -----------------
template<int PT>
__global__ void fps_kernel(const float* __restrict__ posIn, float* __restrict__ posOut,
                           int N, int S)
{
    int b = blockIdx.x, t = threadIdx.x;
    int lane = t & 31, warp = t >> 5;
    float px[PT], py[PT], pz[PT], mind[PT];
    const float* p = posIn + (size_t)b*N*3;
    #pragma unroll
    for (int j = 0; j < PT; j++) {
        int i = j*512 + t;
        px[j] = p[3*i]; py[j] = p[3*i+1]; pz[j] = p[3*i+2];
        mind[j] = 3.402823466e38f;
    }
    __shared__ float s_x, s_y, s_z;
    __shared__ float swv[16];
    __shared__ int   swi[16];
    __shared__ int   s_bi;
    if (t == 0) {
        s_x = p[0]; s_y = p[1]; s_z = p[2];
        float* o = posOut + (size_t)b*S*3;
        o[0] = p[0]; o[1] = p[1]; o[2] = p[2];
    }
    __syncthreads();
    for (int s = 1; s < S; s++) {
        float lx = s_x, ly = s_y, lz = s_z;
        float bv = NEGB; int bi = 1 << 30;
        #pragma unroll
        for (int j = 0; j < PT; j++) {
            float dx = __fsub_rn(px[j], lx);
            float dy = __fsub_rn(py[j], ly);
            float dz = __fsub_rn(pz[j], lz);
            float d  = __fadd_rn(__fadd_rn(__fmul_rn(dx,dx), __fmul_rn(dy,dy)), __fmul_rn(dz,dz));
            float m  = fminf(mind[j], d);
            mind[j] = m;
            int gi = j*512 + t;
            if (m > bv || (m == bv && gi < bi)) { bv = m; bi = gi; }
        }
        #pragma unroll
        for (int off = 16; off; off >>= 1) {
            float ov = __shfl_down_sync(0xffffffffu, bv, off);
            int   oi = __shfl_down_sync(0xffffffffu, bi, off);
            if (ov > bv || (ov == bv && oi < bi)) { bv = ov; bi = oi; }
        }
        if (lane == 0) { swv[warp] = bv; swi[warp] = bi; }
        __syncthreads();
        if (t < 32) {
            float v  = (t < 16) ? swv[t] : NEGB;
            int   i2 = (t < 16) ? swi[t] : (1 << 30);
            #pragma unroll
            for (int off = 16; off; off >>= 1) {
                float ov = __shfl_down_sync(0xffffffffu, v, off);
                int   oi = __shfl_down_sync(0xffffffffu, i2, off);
                if (ov > v || (ov == v && oi < i2)) { v = ov; i2 = oi; }
            }
            if (t == 0) s_bi = i2;
        }
        __syncthreads();
        int bidx = s_bi;
        if (t == (bidx & 511)) {
            int j = bidx >> 9;
            s_x = px[j]; s_y = py[j]; s_z = pz[j];
            float* o = posOut + ((size_t)b*S + s)*3;
            o[0] = px[j]; o[1] = py[j]; o[2] = pz[j];
        }
        __syncthreads();
    }
}

// ----------------- radius NN (unchanged, exact) -----------------
__global__ void radius_kernel(const float* __restrict__ posAll, const float* __restrict__ posQ,
                              int N, int M, float r2,
                              int* __restrict__ nidx, int* __restrict__ cnt)
{
    __shared__ unsigned long long cand[8][256];
    __shared__ int scnt[8];
    int warp = threadIdx.x >> 5, lane = threadIdx.x & 31;
    int q = blockIdx.x * 8 + warp;
    int b = q / M;
    if (lane == 0) scnt[warp] = 0;
    __syncwarp();
    const float* qp = posQ + (size_t)q*3;
    float qx = qp[0], qy = qp[1], qz = qp[2];
    const float* p = posAll + (size_t)b*N*3;
    for (int i = lane; i < N; i += 32) {
        float dx = __fsub_rn(qx, p[3*i]);
        float dy = __fsub_rn(qy, p[3*i+1]);
        float dz = __fsub_rn(qz, p[3*i+2]);
        float d2 = __fadd_rn(__fadd_rn(__fmul_rn(dx,dx), __fmul_rn(dy,dy)), __fmul_rn(dz,dz));
        if (d2 <= r2) {
            int pos = atomicAdd(&scnt[warp], 1);
            if (pos < 256)
                cand[warp][pos] = ((unsigned long long)__float_as_uint(d2) << 32) | (unsigned)i;
        }
    }
    __syncwarp();
    int c = scnt[warp]; if (c > 256) c = 256;
    int* out = nidx + (size_t)q*64;
    if (c <= 64) {
        for (int t = lane; t < c; t += 32) out[t] = (int)(cand[warp][t] & 0xffffffffu);
        if (lane == 0) cnt[q] = c;
    } else {
        int slots = (c + 31) >> 5;
        for (int sel = 0; sel < 64; sel++) {
            unsigned long long best = ~0ULL;
            for (int k = 0; k < slots; k++) {
                int j = lane + (k << 5);
                if (j < c) { unsigned long long v = cand[warp][j]; if (v < best) best = v; }
            }
            #pragma unroll
            for (int off = 16; off; off >>= 1) {
                unsigned long long o = __shfl_down_sync(0xffffffffu, best, off);
                if (o < best) best = o;
            }
            best = __shfl_sync(0xffffffffu, best, 0);
            if (lane == 0) out[sel] = (int)(best & 0xffffffffu);
            for (int k = 0; k < slots; k++) {
                int j = lane + (k << 5);
                if (j < c && cand[warp][j] == best) cand[warp][j] = ~0ULL;
            }
        }
        if (lane == 0) cnt[q] = 64;
    }
}

// ============ Stage-1 fully fused: gather + (3->64->64->128) + masked max ====
// one block = one query (64 msgs), 256 threads, ~89KB smem
__global__ __launch_bounds__(256) void s1_fused(const float* __restrict__ pts,
    const float* __restrict__ w1, const float* __restrict__ b1,
    const float* __restrict__ w2, const float* __restrict__ b2,
    const float* __restrict__ w3, const float* __restrict__ b3)
{
    extern __shared__ float sm[];
    float* sW1 = sm;               // 192
    float* sB1 = sW1 + 192;        // 64
    float* sW2 = sB1 + 64;         // 4096
    float* sB2 = sW2 + 4096;       // 64
    float* sW3 = sB2 + 64;         // 8192
    float* sB3 = sW3 + 8192;       // 128
    float* sRel= sB3 + 128;        // 256
    float* sH1 = sRel + 256;       // 64*65
    float* sH2 = sH1 + 4160;       // 64*65
    float* sPart = sH2 + 4160;     // 8*128

    int q = blockIdx.x;
    int b = q >> 11;
    int tid = threadIdx.x;
    for (int i = tid; i < 192;  i += 256) sW1[i] = w1[i];
    for (int i = tid; i < 64;   i += 256) { sB1[i] = b1[i]; sB2[i] = b2[i]; }
    for (int i = tid; i < 4096; i += 256) sW2[i] = w2[i];
    for (int i = tid; i < 8192; i += 256) sW3[i] = w3[i];
    if (tid < 128) sB3[tid] = b3[tid];
    int cnt = g_cnt1[q];
    if (tid < 64) {
        int idx = (tid < cnt) ? g_nidx1[q*64 + tid] : 0;
        const float* sp = pts + ((size_t)b*4096 + idx)*3;
        const float* qp = g_pos1 + (size_t)q*3;
        sRel[tid*4+0] = sp[0] - qp[0];
        sRel[tid*4+1] = sp[1] - qp[1];
        sRel[tid*4+2] = sp[2] - qp[2];
    }
    __syncthreads();
    // layer1: m = tid>>2, 16 cols each
    {
        int m = tid >> 2, j0 = (tid & 3) * 16;
        float rx = sRel[m*4], ry = sRel[m*4+1], rz = sRel[m*4+2];
        #pragma unroll
        for (int j = 0; j < 16; j++) {
            int c = j0 + j;
            float v = fmaf(rz, sW1[128+c], fmaf(ry, sW1[64+c], fmaf(rx, sW1[c], sB1[c])));
            sH1[m*65 + c] = fmaxf(v, 0.f);
        }
    }
    __syncthreads();
    // layer2: 16x16 threads, 4x4 tile
    {
        int tr = tid >> 4, tc = tid & 15;
        float acc[4][4];
        #pragma unroll
        for (int i = 0; i < 4; i++)
            #pragma unroll
            for (int j = 0; j < 4; j++) acc[i][j] = sB2[tc*4 + j];
        #pragma unroll 4
        for (int k = 0; k < 64; k++) {
            float a[4], bb[4];
            #pragma unroll
            for (int i = 0; i < 4; i++) a[i] = sH1[(tr*4+i)*65 + k];
            #pragma unroll
            for (int j = 0; j < 4; j++) bb[j] = sW2[k*64 + tc*4 + j];
            #pragma unroll
            for (int i = 0; i < 4; i++)
                #pragma unroll
                for (int j = 0; j < 4; j++) acc[i][j] = fmaf(a[i], bb[j], acc[i][j]);
        }
        #pragma unroll
        for (int i = 0; i < 4; i++)
            #pragma unroll
            for (int j = 0; j < 4; j++)
                sH2[(tr*4+i)*65 + tc*4 + j] = fmaxf(acc[i][j], 0.f);
    }
    __syncthreads();
    // layer3 + masked max: rt=tid>>5 rows rt*8.., ct=tid&31 cols ct*4..
    {
        int rt = tid >> 5, ct = tid & 31;
        float acc[8][4];
        #pragma unroll
        for (int i = 0; i < 8; i++)
            #pragma unroll
            for (int j = 0; j < 4; j++) acc[i][j] = sB3[ct*4 + j];
        #pragma unroll 4
        for (int k = 0; k < 64; k++) {
            float a[8], bb[4];
            #pragma unroll
            for (int i = 0; i < 8; i++) a[i] = sH2[(rt*8+i)*65 + k];
            #pragma unroll
            for (int j = 0; j < 4; j++) bb[j] = sW3[k*128 + ct*4 + j];
            #pragma unroll
            for (int i = 0; i < 8; i++)
                #pragma unroll
                for (int j = 0; j < 4; j++) acc[i][j] = fmaf(a[i], bb[j], acc[i][j]);
        }
        float mx[4] = {NEGB, NEGB, NEGB, NEGB};
        #pragma unroll
        for (int i = 0; i < 8; i++)
            if (rt*8 + i < cnt)
                #pragma unroll
                for (int j = 0; j < 4; j++) mx[j] = fmaxf(mx[j], acc[i][j]);
        #pragma unroll
        for (int j = 0; j < 4; j++) sPart[rt*128 + ct*4 + j] = mx[j];
    }
    __syncthreads();
    if (tid < 128) {
        float m = NEGB;
        #pragma unroll
        for (int r = 0; r < 8; r++) m = fmaxf(m, sPart[r*128 + tid]);
        g_x1[(size_t)q*128 + tid] = fmaxf(m, 0.f);
    }
}

// ============ Stage-2 part A: gather + (131->128->128), write h2 ============
__global__ __launch_bounds__(256) void s2a_fused(
    const float* __restrict__ w1, const float* __restrict__ b1,
    const float* __restrict__ w2, const float* __restrict__ b2,
    float* __restrict__ h2out)
{
    extern __shared__ float sm[];
    float* sW1 = sm;                 // 131*128 = 16768
    float* sB1 = sW1 + 16768;        // 128
    float* sW2 = sB1 + 128;          // 16384
    float* sB2 = sW2 + 16384;        // 128
    float* sA  = sB2 + 128;          // 64*132
    float* sH1 = sA + 8448;          // 64*132

    int q = blockIdx.x;              // 4096
    int b = q >> 9;
    int tid = threadIdx.x;
    for (int i = tid; i < 16768; i += 256) sW1[i] = w1[i];
    for (int i = tid; i < 16384; i += 256) sW2[i] = w2[i];
    if (tid < 128) { sB1[tid] = b1[tid]; sB2[tid] = b2[tid]; }
    int cnt = g_cnt2[q];
    // gather: m=tid>>2 message, l4=tid&3 loads 32 feats
    {
        int m = tid >> 2, l4 = tid & 3;
        int idx = (m < cnt) ? g_nidx2[q*64 + m] : 0;
        const float4* src = (const float4*)(g_x1 + ((size_t)b*2048 + idx)*128);
        #pragma unroll
        for (int j = 0; j < 8; j++)
            *((float4*)(sA + m*132 + l4*32 + j*4)) = src[l4*8 + j];
        if (l4 == 0) {
            const float* ps = g_pos1 + ((size_t)b*2048 + idx)*3;
            const float* pq = g_pos2 + (size_t)q*3;
            sA[m*132 + 128] = ps[0] - pq[0];
            sA[m*132 + 129] = ps[1] - pq[1];
            sA[m*132 + 130] = ps[2] - pq[2];
        }
    }
    __syncthreads();
    int rt = tid >> 5, ct = tid & 31;
    // layer1: K=131
    {
        float acc[8][4];
        #pragma unroll
        for (int i = 0; i < 8; i++)
            #pragma unroll
            for (int j = 0; j < 4; j++) acc[i][j] = sB1[ct*4 + j];
        #pragma unroll 4
        for (int k = 0; k < 131; k++) {
            float a[8], bb[4];
            #pragma unroll
            for (int i = 0; i < 8; i++) a[i] = sA[(rt*8+i)*132 + k];
            #pragma unroll
            for (int j = 0; j < 4; j++) bb[j] = sW1[k*128 + ct*4 + j];
            #pragma unroll
            for (int i = 0; i < 8; i++)
                #pragma unroll
                for (int j = 0; j < 4; j++) acc[i][j] = fmaf(a[i], bb[j], acc[i][j]);
        }
        #pragma unroll
        for (int i = 0; i < 8; i++)
            #pragma unroll
            for (int j = 0; j < 4; j++)
                sH1[(rt*8+i)*132 + ct*4 + j] = fmaxf(acc[i][j], 0.f);
    }
    __syncthreads();
    // layer2: K=128 -> global h2
    {
        float acc[8][4];
        #pragma unroll
        for (int i = 0; i < 8; i++)
            #pragma unroll
            for (int j = 0; j < 4; j++) acc[i][j] = sB2[ct*4 + j];
        #pragma unroll 4
        for (int k = 0; k < 128; k++) {
            float a[8], bb[4];
            #pragma unroll
            for (int i = 0; i < 8; i++) a[i] = sH1[(rt*8+i)*132 + k];
            #pragma unroll
            for (int j = 0; j < 4; j++) bb[j] = sW2[k*128 + ct*4 + j];
            #pragma unroll
            for (int i = 0; i < 8; i++)
                #pragma unroll
                for (int j = 0; j < 4; j++) acc[i][j] = fmaf(a[i], bb[j], acc[i][j]);
        }
        #pragma unroll
        for (int i = 0; i < 8; i++) {
            float4 v = make_float4(fmaxf(acc[i][0],0.f), fmaxf(acc[i][1],0.f),
                                   fmaxf(acc[i][2],0.f), fmaxf(acc[i][3],0.f));
            *((float4*)(h2out + ((size_t)q*64 + rt*8 + i)*128 + ct*4)) = v;
        }
    }
}

// ============ Stage-2 part B: (128->256) + masked max -> x2cat ==============
__global__ __launch_bounds__(256) void s2b_fused(
    const float* __restrict__ h2, const float* __restrict__ w3, const float* __restrict__ b3)
{
    extern __shared__ float sm[];
    float* sW3 = sm;                // 128*256 = 32768
    float* sB3 = sW3 + 32768;       // 256
    float* sA  = sB3 + 256;         // 64*132
    float* sPart = sA + 8448;       // 8*256

    int q = blockIdx.x;
    int tid = threadIdx.x;
    for (int i = tid; i < 32768; i += 256) sW3[i] = w3[i];
    if (tid < 256) sB3[tid] = b3[tid];
    {
        int m = tid >> 2, l4 = tid & 3;
        const float4* src = (const float4*)(h2 + ((size_t)q*64 + m)*128);
        #pragma unroll
        for (int j = 0; j < 8; j++)
            *((float4*)(sA + m*132 + l4*32 + j*4)) = src[l4*8 + j];
    }
    __syncthreads();
    int cnt = g_cnt2[q];
    int rt = tid >> 5, ct = tid & 31;     // rows rt*8.., cols ct*8..
    float acc[8][8];
    #pragma unroll
    for (int i = 0; i < 8; i++)
        #pragma unroll
        for (int j = 0; j < 8; j++) acc[i][j] = sB3[ct*8 + j];
    #pragma unroll 2
    for (int k = 0; k < 128; k++) {
        float a[8], bb[8];
        #pragma unroll
        for (int i = 0; i < 8; i++) a[i] = sA[(rt*8+i)*132 + k];
        #pragma unroll
        for (int j = 0; j < 8; j++) bb[j] = sW3[k*256 + ct*8 + j];
        #pragma unroll
        for (int i = 0; i < 8; i++)
            #pragma unroll
            for (int j = 0; j < 8; j++) acc[i][j] = fmaf(a[i], bb[j], acc[i][j]);
    }
    float mx[8];
    #pragma unroll
    for (int j = 0; j < 8; j++) mx[j] = NEGB;
    #pragma unroll
    for (int i = 0; i < 8; i++)
        if (rt*8 + i < cnt)
            #pragma unroll
            for (int j = 0; j < 8; j++) mx[j] = fmaxf(mx[j], acc[i][j]);
    #pragma unroll
    for (int j = 0; j < 8; j++) sPart[rt*256 + ct*8 + j] = mx[j];
    __syncthreads();
    if (tid < 256) {
        float m = NEGB;
        #pragma unroll
        for (int r = 0; r < 8; r++) m = fmaxf(m, sPart[r*256 + tid]);
        g_x2cat[(size_t)q*259 + tid] = fmaxf(m, 0.f);
    }
}

// ----------------- generic tiled GEMM (global MLP + head) --------------------
__global__ void gemm_k(const float* __restrict__ A, const float* __restrict__ W,
                       const float* __restrict__ bias, float* __restrict__ C,
                       int M, int N, int K, int relu)
{
    __shared__ float As[16][132];
    __shared__ float Bs[16][64];
    int tid = threadIdx.x;
    int tr = tid >> 4, tc = tid & 15;
    int row0 = blockIdx.y * 128, col0 = blockIdx.x * 64;
    float acc[8][4];
    #pragma unroll
    for (int i = 0; i < 8; i++)
        #pragma unroll
        for (int j = 0; j < 4; j++) acc[i][j] = 0.f;
    for (int k0 = 0; k0 < K; k0 += 16) {
        #pragma unroll
        for (int l = 0; l < 8; l++) {
            int i = tid + l*256, r = i >> 4, c = i & 15;
            int gr = row0 + r, gc = k0 + c;
            As[c][r] = (gr < M && gc < K) ? A[(size_t)gr*K + gc] : 0.f;
        }
        #pragma unroll
        for (int l = 0; l < 4; l++) {
            int i = tid + l*256, r = i >> 6, c = i & 63;
            int gr = k0 + r, gc = col0 + c;
            Bs[r][c] = (gr < K && gc < N) ? W[(size_t)gr*N + gc] : 0.f;
        }
        __syncthreads();
        #pragma unroll
        for (int k = 0; k < 16; k++) {
            float a[8], bb[4];
            #pragma unroll
            for (int i = 0; i < 8; i++) a[i] = As[k][tr*8 + i];
            #pragma unroll
            for (int j = 0; j < 4; j++) bb[j] = Bs[k][tc*4 + j];
            #pragma unroll
            for (int i = 0; i < 8; i++)
                #pragma unroll
                for (int j = 0; j < 4; j++) acc[i][j] = fmaf(a[i], bb[j], acc[i][j]);
        }
        __syncthreads();
    }
    #pragma unroll
    for (int i = 0; i < 8; i++) {
        int gr = row0 + tr*8 + i;
        if (gr < M) {
            #pragma unroll
            for (int j = 0; j < 4; j++) {
                int gc = col0 + tc*4 + j;
                if (gc < N) {
                    float v = acc[i][j] + bias[gc];
                    if (relu) v = fmaxf(v, 0.f);
                    C[(size_t)gr*N + gc] = v;
                }
            }
        }
    }
}

__global__ void poscat_kernel()
{
    int t = blockIdx.x * 256 + threadIdx.x;
    if (t < 4096*3) {
        int q = t / 3, c = t % 3;
        g_x2cat[(size_t)q*259 + 256 + c] = g_pos2[t];
    }
}

__global__ void gmax_kernel()
{
    int j = blockIdx.x * 256 + threadIdx.x;
    int g = blockIdx.y;
    float m = NEGB;
    const float* base = g_g3 + (size_t)g*128*1024 + j;
    for (int i = 0; i < 128; i++) m = fmaxf(m, base[(size_t)i*1024]);
    g_gmx[(size_t)g*1024 + j] = m;
}

__global__ void final_kernel(float* __restrict__ out)
{
    __shared__ float sm[8][7];
    int t = threadIdx.x;
    if (t < 56) {
        int b = t / 7, c = t % 7;
        float s = g_f3[(b*4)*7+c] + g_f3[(b*4+1)*7+c] + g_f3[(b*4+2)*7+c] + g_f3[(b*4+3)*7+c];
        sm[b][c] = s * 0.25f;
    }
    __syncthreads();
    if (t < 8) {
        float q0 = sm[t][3], q1 = sm[t][4], q2 = sm[t][5], q3 = sm[t][6];
        float nrm = sqrtf(q0*q0 + q1*q1 + q2*q2 + q3*q3);
        float d = fmaxf(nrm, 1e-12f);
        out[t*7+0] = sm[t][0]; out[t*7+1] = sm[t][1]; out[t*7+2] = sm[t][2];
        out[t*7+3] = q0/d; out[t*7+4] = q1/d; out[t*7+5] = q2/d; out[t*7+6] = q3/d;
    }
}

// ----------------- launcher --------------------------------------------------
extern "C" void kernel_launch(void* const* d_in, const int* in_sizes, int n_in,
                              void* d_out, int out_size)
{
    const float* pts  = (const float*)d_in[0];
    const float *s1w1 = (const float*)d_in[1],  *s1b1 = (const float*)d_in[2];
    const float *s1w2 = (const float*)d_in[3],  *s1b2 = (const float*)d_in[4];
    const float *s1w3 = (const float*)d_in[5],  *s1b3 = (const float*)d_in[6];
    const float *s2w1 = (const float*)d_in[7],  *s2b1 = (const float*)d_in[8];
    const float *s2w2 = (const float*)d_in[9],  *s2b2 = (const float*)d_in[10];
    const float *s2w3 = (const float*)d_in[11], *s2b3 = (const float*)d_in[12];
    const float *gw1  = (const float*)d_in[13], *gb1  = (const float*)d_in[14];
    const float *gw2  = (const float*)d_in[15], *gb2  = (const float*)d_in[16];
    const float *gw3  = (const float*)d_in[17], *gb3  = (const float*)d_in[18];
    const float *l1w  = (const float*)d_in[19], *l1b  = (const float*)d_in[20];
    const float *l2w  = (const float*)d_in[21], *l2b  = (const float*)d_in[22];
    const float *l3w  = (const float*)d_in[23], *l3b  = (const float*)d_in[24];

    float *pool, *pos1, *pos2, *x2cat, *g1b, *g2b, *gmx, *f1, *f2;
    int *nidx1, *cnt1, *nidx2, *cnt2;
    cudaGetSymbolAddress((void**)&pool,  g_pool);
    cudaGetSymbolAddress((void**)&pos1,  g_pos1);
    cudaGetSymbolAddress((void**)&pos2,  g_pos2);
    cudaGetSymbolAddress((void**)&nidx1, g_nidx1);
    cudaGetSymbolAddress((void**)&cnt1,  g_cnt1);
    cudaGetSymbolAddress((void**)&nidx2, g_nidx2);
    cudaGetSymbolAddress((void**)&cnt2,  g_cnt2);
    cudaGetSymbolAddress((void**)&x2cat, g_x2cat);
    cudaGetSymbolAddress((void**)&g1b,   g_g1);
    cudaGetSymbolAddress((void**)&g2b,   g_g2);
    cudaGetSymbolAddress((void**)&gmx,   g_gmx);
    cudaGetSymbolAddress((void**)&f1,    g_f1);
    cudaGetSymbolAddress((void**)&f2,    g_f2);
    float* g3b; cudaGetSymbolAddress((void**)&g3b, g_g3);
    float* f3;  cudaGetSymbolAddress((void**)&f3,  g_f3);
    float* h2s2 = pool;

    static int attr_done = 0;
    if (!attr_done) {
        cudaFuncSetAttribute(s1_fused,  cudaFuncAttributeMaxDynamicSharedMemorySize, 89344);
        cudaFuncSetAttribute(s2a_fused, cudaFuncAttributeMaxDynamicSharedMemorySize, 201216);
        cudaFuncSetAttribute(s2b_fused, cudaFuncAttributeMaxDynamicSharedMemorySize, 174080);
        attr_done = 1;
    }

    float r2a = (float)(0.1*0.1), r2b = (float)(0.2*0.2);

    // ---- stage 1 ----
    fps_kernel<8><<<8, 512>>>(pts, pos1, 4096, 2048);
    radius_kernel<<<2048, 256>>>(pts, pos1, 4096, 2048, r2a, nidx1, cnt1);
    s1_fused<<<16384, 256, 89344>>>(pts, s1w1, s1b1, s1w2, s1b2, s1w3, s1b3);

    // ---- stage 2 ----
    fps_kernel<4><<<8, 512>>>(pos1, pos2, 2048, 512);
    radius_kernel<<<512, 256>>>(pos1, pos2, 2048, 512, r2b, nidx2, cnt2);
    s2a_fused<<<4096, 256, 201216>>>(s2w1, s2b1, s2w2, s2b2, h2s2);
    s2b_fused<<<4096, 256, 174080>>>(h2s2, s2w3, s2b3);
    poscat_kernel<<<48, 256>>>();

    // ---- global MLP + pooling + head ----
    gemm_k<<<dim3(4, 32), 256>>>(x2cat, gw1, gb1, g1b, 4096, 256, 259, 1);
    gemm_k<<<dim3(8, 32), 256>>>(g1b, gw2, gb2, g2b, 4096, 512, 256, 1);
    gemm_k<<<dim3(16, 32), 256>>>(g2b, gw3, gb3, g3b, 4096, 1024, 512, 0);
    gmax_kernel<<<dim3(4, 32), 256>>>();
    gemm_k<<<dim3(8, 1), 256>>>(gmx, l1w, l1b, f1, 32, 512, 1024, 1);
    gemm_k<<<dim3(4, 1), 256>>>(f1, l2w, l2b, f2, 32, 256, 512, 1);
    gemm_k<<<dim3(1, 1), 256>>>(f2, l3w, l3b, f3, 32, 7, 256, 0);
    final_kernel<<<1, 64>>>((float*)d_out);
}

// round 5
// speedup vs baseline: 1.2396x; 1.1415x over previous
#include <cuda_runtime.h>
#include <math.h>

#define NEGB -1.0e30f

// ----------------- scratch -----------------
__device__ float g_pool[67108864];
__device__ float g_pos1[8*2048*3];
__device__ float g_pos2[8*512*3];
__device__ int   g_nidx1[8*2048*64];
__device__ int   g_cnt1[8*2048];
__device__ int   g_nidx2[8*512*64];
__device__ int   g_cnt2[8*512];
__device__ float g_x1[8*2048*128];
__device__ float g_x2cat[8*512*259];
__device__ float g_g1[8*512*256];
__device__ float g_g2[8*512*512];
__device__ float g_g3[8*512*1024];
__device__ float g_gmx[32*1024];
__device__ float g_f1[32*512];
__device__ float g_f2[32*256];
__device__ float g_f3[32*7];

// ----------------- FPS v2: 1 barrier/iter, redux.sync warp argmax -----------
// smem: spx[N], spy[N], spz[N], partials[2][16] (u64)
template<int PT>
__global__ __launch_bounds__(512) void fps_kernel(const float* __restrict__ posIn,
                                                  float* __restrict__ posOut,
                                                  int N, int S)
{
    extern __shared__ float sm[];
    float* spx = sm;
    float* spy = sm + N;
    float* spz = sm + 2*N;
    unsigned long long* part = (unsigned long long*)(sm + 3*N);  // [2][16]

    int b = blockIdx.x, t = threadIdx.x;
    int lane = t & 31, warp = t >> 5;
    const float* p = posIn + (size_t)b*N*3;
    float px[PT], py[PT], pz[PT], mind[PT];
    #pragma unroll
    for (int j = 0; j < PT; j++) {
        int i = j*512 + t;
        float x = p[3*i], y = p[3*i+1], z = p[3*i+2];
        px[j] = x; py[j] = y; pz[j] = z;
        spx[i] = x; spy[i] = y; spz[i] = z;
        mind[j] = 3.402823466e38f;
    }
    if (t == 0) {
        float* o = posOut + (size_t)b*S*3;
        o[0] = p[0]; o[1] = p[1]; o[2] = p[2];
    }
    __syncthreads();
    int bidx = 0;
    for (int s = 1; s < S; s++) {
        float lx = spx[bidx], ly = spy[bidx], lz = spz[bidx];
        float bv = NEGB; int bi = 1 << 30;
        #pragma unroll
        for (int j = 0; j < PT; j++) {
            float dx = __fsub_rn(px[j], lx);
            float dy = __fsub_rn(py[j], ly);
            float dz = __fsub_rn(pz[j], lz);
            float d  = __fadd_rn(__fadd_rn(__fmul_rn(dx,dx), __fmul_rn(dy,dy)), __fmul_rn(dz,dz));
            float m  = fminf(mind[j], d);
            mind[j] = m;
            if (m > bv) { bv = m; bi = j*512 + t; }  // ascending gi keeps first max
        }
        // warp argmax via 2x redux.sync (positive-float bits are monotonic)
        unsigned vb = __float_as_uint(bv);
        unsigned vmax = __reduce_max_sync(0xffffffffu, vb);
        int cand = (vb == vmax) ? bi : 0x7fffffff;
        int widx = __reduce_min_sync(0xffffffffu, cand);
        if (lane == 0)
            part[(s & 1)*16 + warp] =
                ((unsigned long long)vmax << 32) | (unsigned)(0xFFFFFFFFu - (unsigned)widx);
        __syncthreads();
        // every thread reduces the 16 partials (broadcast loads, reg tree)
        const unsigned long long* pp = part + (s & 1)*16;
        unsigned long long k0 = pp[0], k1 = pp[1], k2 = pp[2], k3 = pp[3];
        unsigned long long k4 = pp[4], k5 = pp[5], k6 = pp[6], k7 = pp[7];
        unsigned long long k8 = pp[8], k9 = pp[9], ka = pp[10], kb = pp[11];
        unsigned long long kc = pp[12], kd = pp[13], ke = pp[14], kf = pp[15];
        k0 = k0 > k1 ? k0 : k1;  k2 = k2 > k3 ? k2 : k3;
        k4 = k4 > k5 ? k4 : k5;  k6 = k6 > k7 ? k6 : k7;
        k8 = k8 > k9 ? k8 : k9;  ka = ka > kb ? ka : kb;
        kc = kc > kd ? kc : kd;  ke = ke > kf ? ke : kf;
        k0 = k0 > k2 ? k0 : k2;  k4 = k4 > k6 ? k4 : k6;
        k8 = k8 > ka ? k8 : ka;  kc = kc > ke ? kc : ke;
        k0 = k0 > k4 ? k0 : k4;  k8 = k8 > kc ? k8 : kc;
        k0 = k0 > k8 ? k0 : k8;
        bidx = (int)(0xFFFFFFFFu - (unsigned)(k0 & 0xFFFFFFFFu));
        if (t == 0) {
            float* o = posOut + ((size_t)b*S + s)*3;
            o[0] = spx[bidx]; o[1] = spy[bidx]; o[2] = spz[bidx];
        }
    }
}

// ----------------- radius NN (unchanged, exact) -----------------
__global__ void radius_kernel(const float* __restrict__ posAll, const float* __restrict__ posQ,
                              int N, int M, float r2,
                              int* __restrict__ nidx, int* __restrict__ cnt)
{
    __shared__ unsigned long long cand[8][256];
    __shared__ int scnt[8];
    int warp = threadIdx.x >> 5, lane = threadIdx.x & 31;
    int q = blockIdx.x * 8 + warp;
    int b = q / M;
    if (lane == 0) scnt[warp] = 0;
    __syncwarp();
    const float* qp = posQ + (size_t)q*3;
    float qx = qp[0], qy = qp[1], qz = qp[2];
    const float* p = posAll + (size_t)b*N*3;
    for (int i = lane; i < N; i += 32) {
        float dx = __fsub_rn(qx, p[3*i]);
        float dy = __fsub_rn(qy, p[3*i+1]);
        float dz = __fsub_rn(qz, p[3*i+2]);
        float d2 = __fadd_rn(__fadd_rn(__fmul_rn(dx,dx), __fmul_rn(dy,dy)), __fmul_rn(dz,dz));
        if (d2 <= r2) {
            int pos = atomicAdd(&scnt[warp], 1);
            if (pos < 256)
                cand[warp][pos] = ((unsigned long long)__float_as_uint(d2) << 32) | (unsigned)i;
        }
    }
    __syncwarp();
    int c = scnt[warp]; if (c > 256) c = 256;
    int* out = nidx + (size_t)q*64;
    if (c <= 64) {
        for (int t = lane; t < c; t += 32) out[t] = (int)(cand[warp][t] & 0xffffffffu);
        if (lane == 0) cnt[q] = c;
    } else {
        int slots = (c + 31) >> 5;
        for (int sel = 0; sel < 64; sel++) {
            unsigned long long best = ~0ULL;
            for (int k = 0; k < slots; k++) {
                int j = lane + (k << 5);
                if (j < c) { unsigned long long v = cand[warp][j]; if (v < best) best = v; }
            }
            #pragma unroll
            for (int off = 16; off; off >>= 1) {
                unsigned long long o = __shfl_down_sync(0xffffffffu, best, off);
                if (o < best) best = o;
            }
            best = __shfl_sync(0xffffffffu, best, 0);
            if (lane == 0) out[sel] = (int)(best & 0xffffffffu);
            for (int k = 0; k < slots; k++) {
                int j = lane + (k << 5);
                if (j < c && cand[warp][j] == best) cand[warp][j] = ~0ULL;
            }
        }
        if (lane == 0) cnt[q] = 64;
    }
}

// ============ Stage-1 fully fused (unchanged) ============
__global__ __launch_bounds__(256) void s1_fused(const float* __restrict__ pts,
    const float* __restrict__ w1, const float* __restrict__ b1,
    const float* __restrict__ w2, const float* __restrict__ b2,
    const float* __restrict__ w3, const float* __restrict__ b3)
{
    extern __shared__ float sm[];
    float* sW1 = sm;
    float* sB1 = sW1 + 192;
    float* sW2 = sB1 + 64;
    float* sB2 = sW2 + 4096;
    float* sW3 = sB2 + 64;
    float* sB3 = sW3 + 8192;
    float* sRel= sB3 + 128;
    float* sH1 = sRel + 256;
    float* sH2 = sH1 + 4160;
    float* sPart = sH2 + 4160;

    int q = blockIdx.x;
    int b = q >> 11;
    int tid = threadIdx.x;
    for (int i = tid; i < 192;  i += 256) sW1[i] = w1[i];
    for (int i = tid; i < 64;   i += 256) { sB1[i] = b1[i]; sB2[i] = b2[i]; }
    for (int i = tid; i < 4096; i += 256) sW2[i] = w2[i];
    for (int i = tid; i < 8192; i += 256) sW3[i] = w3[i];
    if (tid < 128) sB3[tid] = b3[tid];
    int cnt = g_cnt1[q];
    if (tid < 64) {
        int idx = (tid < cnt) ? g_nidx1[q*64 + tid] : 0;
        const float* sp = pts + ((size_t)b*4096 + idx)*3;
        const float* qp = g_pos1 + (size_t)q*3;
        sRel[tid*4+0] = sp[0] - qp[0];
        sRel[tid*4+1] = sp[1] - qp[1];
        sRel[tid*4+2] = sp[2] - qp[2];
    }
    __syncthreads();
    {
        int m = tid >> 2, j0 = (tid & 3) * 16;
        float rx = sRel[m*4], ry = sRel[m*4+1], rz = sRel[m*4+2];
        #pragma unroll
        for (int j = 0; j < 16; j++) {
            int c = j0 + j;
            float v = fmaf(rz, sW1[128+c], fmaf(ry, sW1[64+c], fmaf(rx, sW1[c], sB1[c])));
            sH1[m*65 + c] = fmaxf(v, 0.f);
        }
    }
    __syncthreads();
    {
        int tr = tid >> 4, tc = tid & 15;
        float acc[4][4];
        #pragma unroll
        for (int i = 0; i < 4; i++)
            #pragma unroll
            for (int j = 0; j < 4; j++) acc[i][j] = sB2[tc*4 + j];
        #pragma unroll 4
        for (int k = 0; k < 64; k++) {
            float a[4], bb[4];
            #pragma unroll
            for (int i = 0; i < 4; i++) a[i] = sH1[(tr*4+i)*65 + k];
            #pragma unroll
            for (int j = 0; j < 4; j++) bb[j] = sW2[k*64 + tc*4 + j];
            #pragma unroll
            for (int i = 0; i < 4; i++)
                #pragma unroll
                for (int j = 0; j < 4; j++) acc[i][j] = fmaf(a[i], bb[j], acc[i][j]);
        }
        #pragma unroll
        for (int i = 0; i < 4; i++)
            #pragma unroll
            for (int j = 0; j < 4; j++)
                sH2[(tr*4+i)*65 + tc*4 + j] = fmaxf(acc[i][j], 0.f);
    }
    __syncthreads();
    {
        int rt = tid >> 5, ct = tid & 31;
        float acc[8][4];
        #pragma unroll
        for (int i = 0; i < 8; i++)
            #pragma unroll
            for (int j = 0; j < 4; j++) acc[i][j] = sB3[ct*4 + j];
        #pragma unroll 4
        for (int k = 0; k < 64; k++) {
            float a[8], bb[4];
            #pragma unroll
            for (int i = 0; i < 8; i++) a[i] = sH2[(rt*8+i)*65 + k];
            #pragma unroll
            for (int j = 0; j < 4; j++) bb[j] = sW3[k*128 + ct*4 + j];
            #pragma unroll
            for (int i = 0; i < 8; i++)
                #pragma unroll
                for (int j = 0; j < 4; j++) acc[i][j] = fmaf(a[i], bb[j], acc[i][j]);
        }
        float mx[4] = {NEGB, NEGB, NEGB, NEGB};
        #pragma unroll
        for (int i = 0; i < 8; i++)
            if (rt*8 + i < cnt)
                #pragma unroll
                for (int j = 0; j < 4; j++) mx[j] = fmaxf(mx[j], acc[i][j]);
        #pragma unroll
        for (int j = 0; j < 4; j++) sPart[rt*128 + ct*4 + j] = mx[j];
    }
    __syncthreads();
    if (tid < 128) {
        float m = NEGB;
        #pragma unroll
        for (int r = 0; r < 8; r++) m = fmaxf(m, sPart[r*128 + tid]);
        g_x1[(size_t)q*128 + tid] = fmaxf(m, 0.f);
    }
}

// ============ Stage-2 part A (unchanged) ============
__global__ __launch_bounds__(256) void s2a_fused(
    const float* __restrict__ w1, const float* __restrict__ b1,
    const float* __restrict__ w2, const float* __restrict__ b2,
    float* __restrict__ h2out)
{
    extern __shared__ float sm[];
    float* sW1 = sm;
    float* sB1 = sW1 + 16768;
    float* sW2 = sB1 + 128;
    float* sB2 = sW2 + 16384;
    float* sA  = sB2 + 128;
    float* sH1 = sA + 8448;

    int q = blockIdx.x;
    int b = q >> 9;
    int tid = threadIdx.x;
    for (int i = tid; i < 16768; i += 256) sW1[i] = w1[i];
    for (int i = tid; i < 16384; i += 256) sW2[i] = w2[i];
    if (tid < 128) { sB1[tid] = b1[tid]; sB2[tid] = b2[tid]; }
    int cnt = g_cnt2[q];
    {
        int m = tid >> 2, l4 = tid & 3;
        int idx = (m < cnt) ? g_nidx2[q*64 + m] : 0;
        const float4* src = (const float4*)(g_x1 + ((size_t)b*2048 + idx)*128);
        #pragma unroll
        for (int j = 0; j < 8; j++)
            *((float4*)(sA + m*132 + l4*32 + j*4)) = src[l4*8 + j];
        if (l4 == 0) {
            const float* ps = g_pos1 + ((size_t)b*2048 + idx)*3;
            const float* pq = g_pos2 + (size_t)q*3;
            sA[m*132 + 128] = ps[0] - pq[0];
            sA[m*132 + 129] = ps[1] - pq[1];
            sA[m*132 + 130] = ps[2] - pq[2];
        }
    }
    __syncthreads();
    int rt = tid >> 5, ct = tid & 31;
    {
        float acc[8][4];
        #pragma unroll
        for (int i = 0; i < 8; i++)
            #pragma unroll
            for (int j = 0; j < 4; j++) acc[i][j] = sB1[ct*4 + j];
        #pragma unroll 4
        for (int k = 0; k < 131; k++) {
            float a[8], bb[4];
            #pragma unroll
            for (int i = 0; i < 8; i++) a[i] = sA[(rt*8+i)*132 + k];
            #pragma unroll
            for (int j = 0; j < 4; j++) bb[j] = sW1[k*128 + ct*4 + j];
            #pragma unroll
            for (int i = 0; i < 8; i++)
                #pragma unroll
                for (int j = 0; j < 4; j++) acc[i][j] = fmaf(a[i], bb[j], acc[i][j]);
        }
        #pragma unroll
        for (int i = 0; i < 8; i++)
            #pragma unroll
            for (int j = 0; j < 4; j++)
                sH1[(rt*8+i)*132 + ct*4 + j] = fmaxf(acc[i][j], 0.f);
    }
    __syncthreads();
    {
        float acc[8][4];
        #pragma unroll
        for (int i = 0; i < 8; i++)
            #pragma unroll
            for (int j = 0; j < 4; j++) acc[i][j] = sB2[ct*4 + j];
        #pragma unroll 4
        for (int k = 0; k < 128; k++) {
            float a[8], bb[4];
            #pragma unroll
            for (int i = 0; i < 8; i++) a[i] = sH1[(rt*8+i)*132 + k];
            #pragma unroll
            for (int j = 0; j < 4; j++) bb[j] = sW2[k*128 + ct*4 + j];
            #pragma unroll
            for (int i = 0; i < 8; i++)
                #pragma unroll
                for (int j = 0; j < 4; j++) acc[i][j] = fmaf(a[i], bb[j], acc[i][j]);
        }
        #pragma unroll
        for (int i = 0; i < 8; i++) {
            float4 v = make_float4(fmaxf(acc[i][0],0.f), fmaxf(acc[i][1],0.f),
                                   fmaxf(acc[i][2],0.f), fmaxf(acc[i][3],0.f));
            *((float4*)(h2out + ((size_t)q*64 + rt*8 + i)*128 + ct*4)) = v;
        }
    }
}

// ============ Stage-2 part B (unchanged) ============
__global__ __launch_bounds__(256) void s2b_fused(
    const float* __restrict__ h2, const float* __restrict__ w3, const float* __restrict__ b3)
{
    extern __shared__ float sm[];
    float* sW3 = sm;
    float* sB3 = sW3 + 32768;
    float* sA  = sB3 + 256;
    float* sPart = sA + 8448;

    int q = blockIdx.x;
    int tid = threadIdx.x;
    for (int i = tid; i < 32768; i += 256) sW3[i] = w3[i];
    if (tid < 256) sB3[tid] = b3[tid];
    {
        int m = tid >> 2, l4 = tid & 3;
        const float4* src = (const float4*)(h2 + ((size_t)q*64 + m)*128);
        #pragma unroll
        for (int j = 0; j < 8; j++)
            *((float4*)(sA + m*132 + l4*32 + j*4)) = src[l4*8 + j];
    }
    __syncthreads();
    int cnt = g_cnt2[q];
    int rt = tid >> 5, ct = tid & 31;
    float acc[8][8];
    #pragma unroll
    for (int i = 0; i < 8; i++)
        #pragma unroll
        for (int j = 0; j < 8; j++) acc[i][j] = sB3[ct*8 + j];
    #pragma unroll 2
    for (int k = 0; k < 128; k++) {
        float a[8], bb[8];
        #pragma unroll
        for (int i = 0; i < 8; i++) a[i] = sA[(rt*8+i)*132 + k];
        #pragma unroll
        for (int j = 0; j < 8; j++) bb[j] = sW3[k*256 + ct*8 + j];
        #pragma unroll
        for (int i = 0; i < 8; i++)
            #pragma unroll
            for (int j = 0; j < 8; j++) acc[i][j] = fmaf(a[i], bb[j], acc[i][j]);
    }
    float mx[8];
    #pragma unroll
    for (int j = 0; j < 8; j++) mx[j] = NEGB;
    #pragma unroll
    for (int i = 0; i < 8; i++)
        if (rt*8 + i < cnt)
            #pragma unroll
            for (int j = 0; j < 8; j++) mx[j] = fmaxf(mx[j], acc[i][j]);
    #pragma unroll
    for (int j = 0; j < 8; j++) sPart[rt*256 + ct*8 + j] = mx[j];
    __syncthreads();
    if (tid < 256) {
        float m = NEGB;
        #pragma unroll
        for (int r = 0; r < 8; r++) m = fmaxf(m, sPart[r*256 + tid]);
        g_x2cat[(size_t)q*259 + tid] = fmaxf(m, 0.f);
    }
}

// ----------------- generic tiled GEMM (unchanged) ----------------------------
__global__ void gemm_k(const float* __restrict__ A, const float* __restrict__ W,
                       const float* __restrict__ bias, float* __restrict__ C,
                       int M, int N, int K, int relu)
{
    __shared__ float As[16][132];
    __shared__ float Bs[16][64];
    int tid = threadIdx.x;
    int tr = tid >> 4, tc = tid & 15;
    int row0 = blockIdx.y * 128, col0 = blockIdx.x * 64;
    float acc[8][4];
    #pragma unroll
    for (int i = 0; i < 8; i++)
        #pragma unroll
        for (int j = 0; j < 4; j++) acc[i][j] = 0.f;
    for (int k0 = 0; k0 < K; k0 += 16) {
        #pragma unroll
        for (int l = 0; l < 8; l++) {
            int i = tid + l*256, r = i >> 4, c = i & 15;
            int gr = row0 + r, gc = k0 + c;
            As[c][r] = (gr < M && gc < K) ? A[(size_t)gr*K + gc] : 0.f;
        }
        #pragma unroll
        for (int l = 0; l < 4; l++) {
            int i = tid + l*256, r = i >> 6, c = i & 63;
            int gr = k0 + r, gc = col0 + c;
            Bs[r][c] = (gr < K && gc < N) ? W[(size_t)gr*N + gc] : 0.f;
        }
        __syncthreads();
        #pragma unroll
        for (int k = 0; k < 16; k++) {
            float a[8], bb[4];
            #pragma unroll
            for (int i = 0; i < 8; i++) a[i] = As[k][tr*8 + i];
            #pragma unroll
            for (int j = 0; j < 4; j++) bb[j] = Bs[k][tc*4 + j];
            #pragma unroll
            for (int i = 0; i < 8; i++)
                #pragma unroll
                for (int j = 0; j < 4; j++) acc[i][j] = fmaf(a[i], bb[j], acc[i][j]);
        }
        __syncthreads();
    }
    #pragma unroll
    for (int i = 0; i < 8; i++) {
        int gr = row0 + tr*8 + i;
        if (gr < M) {
            #pragma unroll
            for (int j = 0; j < 4; j++) {
                int gc = col0 + tc*4 + j;
                if (gc < N) {
                    float v = acc[i][j] + bias[gc];
                    if (relu) v = fmaxf(v, 0.f);
                    C[(size_t)gr*N + gc] = v;
                }
            }
        }
    }
}

__global__ void poscat_kernel()
{
    int t = blockIdx.x * 256 + threadIdx.x;
    if (t < 4096*3) {
        int q = t / 3, c = t % 3;
        g_x2cat[(size_t)q*259 + 256 + c] = g_pos2[t];
    }
}

__global__ void gmax_kernel()
{
    int j = blockIdx.x * 256 + threadIdx.x;
    int g = blockIdx.y;
    float m = NEGB;
    const float* base = g_g3 + (size_t)g*128*1024 + j;
    for (int i = 0; i < 128; i++) m = fmaxf(m, base[(size_t)i*1024]);
    g_gmx[(size_t)g*1024 + j] = m;
}

__global__ void final_kernel(float* __restrict__ out)
{
    __shared__ float sm[8][7];
    int t = threadIdx.x;
    if (t < 56) {
        int b = t / 7, c = t % 7;
        float s = g_f3[(b*4)*7+c] + g_f3[(b*4+1)*7+c] + g_f3[(b*4+2)*7+c] + g_f3[(b*4+3)*7+c];
        sm[b][c] = s * 0.25f;
    }
    __syncthreads();
    if (t < 8) {
        float q0 = sm[t][3], q1 = sm[t][4], q2 = sm[t][5], q3 = sm[t][6];
        float nrm = sqrtf(q0*q0 + q1*q1 + q2*q2 + q3*q3);
        float d = fmaxf(nrm, 1e-12f);
        out[t*7+0] = sm[t][0]; out[t*7+1] = sm[t][1]; out[t*7+2] = sm[t][2];
        out[t*7+3] = q0/d; out[t*7+4] = q1/d; out[t*7+5] = q2/d; out[t*7+6] = q3/d;
    }
}

// ----------------- launcher --------------------------------------------------
extern "C" void kernel_launch(void* const* d_in, const int* in_sizes, int n_in,
                              void* d_out, int out_size)
{
    const float* pts  = (const float*)d_in[0];
    const float *s1w1 = (const float*)d_in[1],  *s1b1 = (const float*)d_in[2];
    const float *s1w2 = (const float*)d_in[3],  *s1b2 = (const float*)d_in[4];
    const float *s1w3 = (const float*)d_in[5],  *s1b3 = (const float*)d_in[6];
    const float *s2w1 = (const float*)d_in[7],  *s2b1 = (const float*)d_in[8];
    const float *s2w2 = (const float*)d_in[9],  *s2b2 = (const float*)d_in[10];
    const float *s2w3 = (const float*)d_in[11], *s2b3 = (const float*)d_in[12];
    const float *gw1  = (const float*)d_in[13], *gb1  = (const float*)d_in[14];
    const float *gw2  = (const float*)d_in[15], *gb2  = (const float*)d_in[16];
    const float *gw3  = (const float*)d_in[17], *gb3  = (const float*)d_in[18];
    const float *l1w  = (const float*)d_in[19], *l1b  = (const float*)d_in[20];
    const float *l2w  = (const float*)d_in[21], *l2b  = (const float*)d_in[22];
    const float *l3w  = (const float*)d_in[23], *l3b  = (const float*)d_in[24];

    float *pool, *pos1, *pos2, *x2cat, *g1b, *g2b, *gmx, *f1, *f2;
    int *nidx1, *cnt1, *nidx2, *cnt2;
    cudaGetSymbolAddress((void**)&pool,  g_pool);
    cudaGetSymbolAddress((void**)&pos1,  g_pos1);
    cudaGetSymbolAddress((void**)&pos2,  g_pos2);
    cudaGetSymbolAddress((void**)&nidx1, g_nidx1);
    cudaGetSymbolAddress((void**)&cnt1,  g_cnt1);
    cudaGetSymbolAddress((void**)&nidx2, g_nidx2);
    cudaGetSymbolAddress((void**)&cnt2,  g_cnt2);
    cudaGetSymbolAddress((void**)&x2cat, g_x2cat);
    cudaGetSymbolAddress((void**)&g1b,   g_g1);
    cudaGetSymbolAddress((void**)&g2b,   g_g2);
    cudaGetSymbolAddress((void**)&gmx,   g_gmx);
    cudaGetSymbolAddress((void**)&f1,    g_f1);
    cudaGetSymbolAddress((void**)&f2,    g_f2);
    float* g3b; cudaGetSymbolAddress((void**)&g3b, g_g3);
    float* f3;  cudaGetSymbolAddress((void**)&f3,  g_f3);
    float* h2s2 = pool;

    static int attr_done = 0;
    if (!attr_done) {
        cudaFuncSetAttribute(fps_kernel<8>, cudaFuncAttributeMaxDynamicSharedMemorySize, 4096*12 + 512);
        cudaFuncSetAttribute(fps_kernel<4>, cudaFuncAttributeMaxDynamicSharedMemorySize, 2048*12 + 512);
        cudaFuncSetAttribute(s1_fused,  cudaFuncAttributeMaxDynamicSharedMemorySize, 89344);
        cudaFuncSetAttribute(s2a_fused, cudaFuncAttributeMaxDynamicSharedMemorySize, 201216);
        cudaFuncSetAttribute(s2b_fused, cudaFuncAttributeMaxDynamicSharedMemorySize, 174080);
        attr_done = 1;
    }

    float r2a = (float)(0.1*0.1), r2b = (float)(0.2*0.2);

    // ---- stage 1 ----
    fps_kernel<8><<<8, 512, 4096*12 + 512>>>(pts, pos1, 4096, 2048);
    radius_kernel<<<2048, 256>>>(pts, pos1, 4096, 2048, r2a, nidx1, cnt1);
    s1_fused<<<16384, 256, 89344>>>(pts, s1w1, s1b1, s1w2, s1b2, s1w3, s1b3);

    // ---- stage 2 ----
    fps_kernel<4><<<8, 512, 2048*12 + 512>>>(pos1, pos2, 2048, 512);
    radius_kernel<<<512, 256>>>(pos1, pos2, 2048, 512, r2b, nidx2, cnt2);
    s2a_fused<<<4096, 256, 201216>>>(s2w1, s2b1, s2w2, s2b2, h2s2);
    s2b_fused<<<4096, 256, 174080>>>(h2s2, s2w3, s2b3);
    poscat_kernel<<<48, 256>>>();

    // ---- global MLP + pooling + head ----
    gemm_k<<<dim3(4, 32), 256>>>(x2cat, gw1, gb1, g1b, 4096, 256, 259, 1);
    gemm_k<<<dim3(8, 32), 256>>>(g1b, gw2, gb2, g2b, 4096, 512, 256, 1);
    gemm_k<<<dim3(16, 32), 256>>>(g2b, gw3, gb3, g3b, 4096, 1024, 512, 0);
    gmax_kernel<<<dim3(4, 32), 256>>>();
    gemm_k<<<dim3(8, 1), 256>>>(gmx, l1w, l1b, f1, 32, 512, 1024, 1);
    gemm_k<<<dim3(4, 1), 256>>>(f1, l2w, l2b, f2, 32, 256, 512, 1);
    gemm_k<<<dim3(1, 1), 256>>>(f2, l3w, l3b, f3, 32, 7, 256, 0);
    final_kernel<<<1, 64>>>((float*)d_out);
}

// round 6
// speedup vs baseline: 1.3129x; 1.0591x over previous
#include <cuda_runtime.h>
#include <math.h>

#define NEGB -1.0e30f

// ----------------- scratch -----------------
__device__ float g_pool[67108864];
__device__ float g_pos1[8*2048*3];
__device__ float g_pos2[8*512*3];
__device__ int   g_nidx1[8*2048*64];
__device__ int   g_cnt1[8*2048];
__device__ int   g_nidx2[8*512*64];
__device__ int   g_cnt2[8*512];
__device__ float g_x1[8*2048*128];
__device__ float g_x2cat[8*512*259];
__device__ float g_g1[8*512*256];
__device__ float g_g2[8*512*512];
__device__ float g_g3[8*512*1024];
__device__ float g_gmx[32*1024];
__device__ float g_f1[32*512];
__device__ float g_f2[32*256];
__device__ float g_f3[32*7];

// ----------------- FPS v3: 128 threads, PT pts/thread, 4 partials ------------
// smem: spx[N], spy[N], spz[N], partials[2][4] (u64)
template<int PT>
__global__ __launch_bounds__(128) void fps_kernel(const float* __restrict__ posIn,
                                                  float* __restrict__ posOut,
                                                  int N, int S)
{
    extern __shared__ float sm[];
    float* spx = sm;
    float* spy = sm + N;
    float* spz = sm + 2*N;
    unsigned long long* part = (unsigned long long*)(sm + 3*N);  // [2][4]

    int b = blockIdx.x, t = threadIdx.x;
    int lane = t & 31, warp = t >> 5;
    const float* p = posIn + (size_t)b*N*3;
    float px[PT], py[PT], pz[PT], mind[PT];
    #pragma unroll
    for (int j = 0; j < PT; j++) {
        int i = j*128 + t;
        float x = p[3*i], y = p[3*i+1], z = p[3*i+2];
        px[j] = x; py[j] = y; pz[j] = z;
        spx[i] = x; spy[i] = y; spz[i] = z;
        mind[j] = 3.402823466e38f;
    }
    if (t == 0) {
        float* o = posOut + (size_t)b*S*3;
        o[0] = p[0]; o[1] = p[1]; o[2] = p[2];
    }
    __syncthreads();
    int bidx = 0;
    for (int s = 1; s < S; s++) {
        float lx = spx[bidx], ly = spy[bidx], lz = spz[bidx];
        float bv = NEGB; int bi = 1 << 30;
        #pragma unroll
        for (int j = 0; j < PT; j++) {
            float dx = __fsub_rn(px[j], lx);
            float dy = __fsub_rn(py[j], ly);
            float dz = __fsub_rn(pz[j], lz);
            float d  = __fadd_rn(__fadd_rn(__fmul_rn(dx,dx), __fmul_rn(dy,dy)), __fmul_rn(dz,dz));
            float m  = fminf(mind[j], d);
            mind[j] = m;
            if (m > bv) { bv = m; bi = j*128 + t; }  // ascending gi keeps first max
        }
        // warp argmax via 2x redux.sync (nonneg float bits are monotonic)
        unsigned vb = __float_as_uint(bv);
        unsigned vmax = __reduce_max_sync(0xffffffffu, vb);
        int cand = (vb == vmax) ? bi : 0x7fffffff;
        int widx = __reduce_min_sync(0xffffffffu, cand);
        if (lane == 0)
            part[(s & 1)*4 + warp] =
                ((unsigned long long)vmax << 32) | (unsigned)(0xFFFFFFFFu - (unsigned)widx);
        __syncthreads();
        const unsigned long long* pp = part + (s & 1)*4;
        unsigned long long k0 = pp[0], k1 = pp[1], k2 = pp[2], k3 = pp[3];
        k0 = k0 > k1 ? k0 : k1;
        k2 = k2 > k3 ? k2 : k3;
        k0 = k0 > k2 ? k0 : k2;
        bidx = (int)(0xFFFFFFFFu - (unsigned)(k0 & 0xFFFFFFFFu));
        if (t == 0) {
            float* o = posOut + ((size_t)b*S + s)*3;
            o[0] = spx[bidx]; o[1] = spy[bidx]; o[2] = spz[bidx];
        }
    }
}

// ----------------- radius NN (unchanged, exact) -----------------
__global__ void radius_kernel(const float* __restrict__ posAll, const float* __restrict__ posQ,
                              int N, int M, float r2,
                              int* __restrict__ nidx, int* __restrict__ cnt)
{
    __shared__ unsigned long long cand[8][256];
    __shared__ int scnt[8];
    int warp = threadIdx.x >> 5, lane = threadIdx.x & 31;
    int q = blockIdx.x * 8 + warp;
    int b = q / M;
    if (lane == 0) scnt[warp] = 0;
    __syncwarp();
    const float* qp = posQ + (size_t)q*3;
    float qx = qp[0], qy = qp[1], qz = qp[2];
    const float* p = posAll + (size_t)b*N*3;
    for (int i = lane; i < N; i += 32) {
        float dx = __fsub_rn(qx, p[3*i]);
        float dy = __fsub_rn(qy, p[3*i+1]);
        float dz = __fsub_rn(qz, p[3*i+2]);
        float d2 = __fadd_rn(__fadd_rn(__fmul_rn(dx,dx), __fmul_rn(dy,dy)), __fmul_rn(dz,dz));
        if (d2 <= r2) {
            int pos = atomicAdd(&scnt[warp], 1);
            if (pos < 256)
                cand[warp][pos] = ((unsigned long long)__float_as_uint(d2) << 32) | (unsigned)i;
        }
    }
    __syncwarp();
    int c = scnt[warp]; if (c > 256) c = 256;
    int* out = nidx + (size_t)q*64;
    if (c <= 64) {
        for (int t = lane; t < c; t += 32) out[t] = (int)(cand[warp][t] & 0xffffffffu);
        if (lane == 0) cnt[q] = c;
    } else {
        int slots = (c + 31) >> 5;
        for (int sel = 0; sel < 64; sel++) {
            unsigned long long best = ~0ULL;
            for (int k = 0; k < slots; k++) {
                int j = lane + (k << 5);
                if (j < c) { unsigned long long v = cand[warp][j]; if (v < best) best = v; }
            }
            #pragma unroll
            for (int off = 16; off; off >>= 1) {
                unsigned long long o = __shfl_down_sync(0xffffffffu, best, off);
                if (o < best) best = o;
            }
            best = __shfl_sync(0xffffffffu, best, 0);
            if (lane == 0) out[sel] = (int)(best & 0xffffffffu);
            for (int k = 0; k < slots; k++) {
                int j = lane + (k << 5);
                if (j < c && cand[warp][j] == best) cand[warp][j] = ~0ULL;
            }
        }
        if (lane == 0) cnt[q] = 64;
    }
}

// ============ Stage-1 fully fused (unchanged) ============
__global__ __launch_bounds__(256) void s1_fused(const float* __restrict__ pts,
    const float* __restrict__ w1, const float* __restrict__ b1,
    const float* __restrict__ w2, const float* __restrict__ b2,
    const float* __restrict__ w3, const float* __restrict__ b3)
{
    extern __shared__ float sm[];
    float* sW1 = sm;
    float* sB1 = sW1 + 192;
    float* sW2 = sB1 + 64;
    float* sB2 = sW2 + 4096;
    float* sW3 = sB2 + 64;
    float* sB3 = sW3 + 8192;
    float* sRel= sB3 + 128;
    float* sH1 = sRel + 256;
    float* sH2 = sH1 + 4160;
    float* sPart = sH2 + 4160;

    int q = blockIdx.x;
    int b = q >> 11;
    int tid = threadIdx.x;
    for (int i = tid; i < 192;  i += 256) sW1[i] = w1[i];
    for (int i = tid; i < 64;   i += 256) { sB1[i] = b1[i]; sB2[i] = b2[i]; }
    for (int i = tid; i < 4096; i += 256) sW2[i] = w2[i];
    for (int i = tid; i < 8192; i += 256) sW3[i] = w3[i];
    if (tid < 128) sB3[tid] = b3[tid];
    int cnt = g_cnt1[q];
    if (tid < 64) {
        int idx = (tid < cnt) ? g_nidx1[q*64 + tid] : 0;
        const float* sp = pts + ((size_t)b*4096 + idx)*3;
        const float* qp = g_pos1 + (size_t)q*3;
        sRel[tid*4+0] = sp[0] - qp[0];
        sRel[tid*4+1] = sp[1] - qp[1];
        sRel[tid*4+2] = sp[2] - qp[2];
    }
    __syncthreads();
    {
        int m = tid >> 2, j0 = (tid & 3) * 16;
        float rx = sRel[m*4], ry = sRel[m*4+1], rz = sRel[m*4+2];
        #pragma unroll
        for (int j = 0; j < 16; j++) {
            int c = j0 + j;
            float v = fmaf(rz, sW1[128+c], fmaf(ry, sW1[64+c], fmaf(rx, sW1[c], sB1[c])));
            sH1[m*65 + c] = fmaxf(v, 0.f);
        }
    }
    __syncthreads();
    {
        int tr = tid >> 4, tc = tid & 15;
        float acc[4][4];
        #pragma unroll
        for (int i = 0; i < 4; i++)
            #pragma unroll
            for (int j = 0; j < 4; j++) acc[i][j] = sB2[tc*4 + j];
        #pragma unroll 4
        for (int k = 0; k < 64; k++) {
            float a[4], bb[4];
            #pragma unroll
            for (int i = 0; i < 4; i++) a[i] = sH1[(tr*4+i)*65 + k];
            #pragma unroll
            for (int j = 0; j < 4; j++) bb[j] = sW2[k*64 + tc*4 + j];
            #pragma unroll
            for (int i = 0; i < 4; i++)
                #pragma unroll
                for (int j = 0; j < 4; j++) acc[i][j] = fmaf(a[i], bb[j], acc[i][j]);
        }
        #pragma unroll
        for (int i = 0; i < 4; i++)
            #pragma unroll
            for (int j = 0; j < 4; j++)
                sH2[(tr*4+i)*65 + tc*4 + j] = fmaxf(acc[i][j], 0.f);
    }
    __syncthreads();
    {
        int rt = tid >> 5, ct = tid & 31;
        float acc[8][4];
        #pragma unroll
        for (int i = 0; i < 8; i++)
            #pragma unroll
            for (int j = 0; j < 4; j++) acc[i][j] = sB3[ct*4 + j];
        #pragma unroll 4
        for (int k = 0; k < 64; k++) {
            float a[8], bb[4];
            #pragma unroll
            for (int i = 0; i < 8; i++) a[i] = sH2[(rt*8+i)*65 + k];
            #pragma unroll
            for (int j = 0; j < 4; j++) bb[j] = sW3[k*128 + ct*4 + j];
            #pragma unroll
            for (int i = 0; i < 8; i++)
                #pragma unroll
                for (int j = 0; j < 4; j++) acc[i][j] = fmaf(a[i], bb[j], acc[i][j]);
        }
        float mx[4] = {NEGB, NEGB, NEGB, NEGB};
        #pragma unroll
        for (int i = 0; i < 8; i++)
            if (rt*8 + i < cnt)
                #pragma unroll
                for (int j = 0; j < 4; j++) mx[j] = fmaxf(mx[j], acc[i][j]);
        #pragma unroll
        for (int j = 0; j < 4; j++) sPart[rt*128 + ct*4 + j] = mx[j];
    }
    __syncthreads();
    if (tid < 128) {
        float m = NEGB;
        #pragma unroll
        for (int r = 0; r < 8; r++) m = fmaxf(m, sPart[r*128 + tid]);
        g_x1[(size_t)q*128 + tid] = fmaxf(m, 0.f);
    }
}

// ============ Stage-2 part A (unchanged) ============
__global__ __launch_bounds__(256) void s2a_fused(
    const float* __restrict__ w1, const float* __restrict__ b1,
    const float* __restrict__ w2, const float* __restrict__ b2,
    float* __restrict__ h2out)
{
    extern __shared__ float sm[];
    float* sW1 = sm;
    float* sB1 = sW1 + 16768;
    float* sW2 = sB1 + 128;
    float* sB2 = sW2 + 16384;
    float* sA  = sB2 + 128;
    float* sH1 = sA + 8448;

    int q = blockIdx.x;
    int b = q >> 9;
    int tid = threadIdx.x;
    for (int i = tid; i < 16768; i += 256) sW1[i] = w1[i];
    for (int i = tid; i < 16384; i += 256) sW2[i] = w2[i];
    if (tid < 128) { sB1[tid] = b1[tid]; sB2[tid] = b2[tid]; }
    int cnt = g_cnt2[q];
    {
        int m = tid >> 2, l4 = tid & 3;
        int idx = (m < cnt) ? g_nidx2[q*64 + m] : 0;
        const float4* src = (const float4*)(g_x1 + ((size_t)b*2048 + idx)*128);
        #pragma unroll
        for (int j = 0; j < 8; j++)
            *((float4*)(sA + m*132 + l4*32 + j*4)) = src[l4*8 + j];
        if (l4 == 0) {
            const float* ps = g_pos1 + ((size_t)b*2048 + idx)*3;
            const float* pq = g_pos2 + (size_t)q*3;
            sA[m*132 + 128] = ps[0] - pq[0];
            sA[m*132 + 129] = ps[1] - pq[1];
            sA[m*132 + 130] = ps[2] - pq[2];
        }
    }
    __syncthreads();
    int rt = tid >> 5, ct = tid & 31;
    {
        float acc[8][4];
        #pragma unroll
        for (int i = 0; i < 8; i++)
            #pragma unroll
            for (int j = 0; j < 4; j++) acc[i][j] = sB1[ct*4 + j];
        #pragma unroll 4
        for (int k = 0; k < 131; k++) {
            float a[8], bb[4];
            #pragma unroll
            for (int i = 0; i < 8; i++) a[i] = sA[(rt*8+i)*132 + k];
            #pragma unroll
            for (int j = 0; j < 4; j++) bb[j] = sW1[k*128 + ct*4 + j];
            #pragma unroll
            for (int i = 0; i < 8; i++)
                #pragma unroll
                for (int j = 0; j < 4; j++) acc[i][j] = fmaf(a[i], bb[j], acc[i][j]);
        }
        #pragma unroll
        for (int i = 0; i < 8; i++)
            #pragma unroll
            for (int j = 0; j < 4; j++)
                sH1[(rt*8+i)*132 + ct*4 + j] = fmaxf(acc[i][j], 0.f);
    }
    __syncthreads();
    {
        float acc[8][4];
        #pragma unroll
        for (int i = 0; i < 8; i++)
            #pragma unroll
            for (int j = 0; j < 4; j++) acc[i][j] = sB2[ct*4 + j];
        #pragma unroll 4
        for (int k = 0; k < 128; k++) {
            float a[8], bb[4];
            #pragma unroll
            for (int i = 0; i < 8; i++) a[i] = sH1[(rt*8+i)*132 + k];
            #pragma unroll
            for (int j = 0; j < 4; j++) bb[j] = sW2[k*128 + ct*4 + j];
            #pragma unroll
            for (int i = 0; i < 8; i++)
                #pragma unroll
                for (int j = 0; j < 4; j++) acc[i][j] = fmaf(a[i], bb[j], acc[i][j]);
        }
        #pragma unroll
        for (int i = 0; i < 8; i++) {
            float4 v = make_float4(fmaxf(acc[i][0],0.f), fmaxf(acc[i][1],0.f),
                                   fmaxf(acc[i][2],0.f), fmaxf(acc[i][3],0.f));
            *((float4*)(h2out + ((size_t)q*64 + rt*8 + i)*128 + ct*4)) = v;
        }
    }
}

// ============ Stage-2 part B (unchanged) ============
__global__ __launch_bounds__(256) void s2b_fused(
    const float* __restrict__ h2, const float* __restrict__ w3, const float* __restrict__ b3)
{
    extern __shared__ float sm[];
    float* sW3 = sm;
    float* sB3 = sW3 + 32768;
    float* sA  = sB3 + 256;
    float* sPart = sA + 8448;

    int q = blockIdx.x;
    int tid = threadIdx.x;
    for (int i = tid; i < 32768; i += 256) sW3[i] = w3[i];
    if (tid < 256) sB3[tid] = b3[tid];
    {
        int m = tid >> 2, l4 = tid & 3;
        const float4* src = (const float4*)(h2 + ((size_t)q*64 + m)*128);
        #pragma unroll
        for (int j = 0; j < 8; j++)
            *((float4*)(sA + m*132 + l4*32 + j*4)) = src[l4*8 + j];
    }
    __syncthreads();
    int cnt = g_cnt2[q];
    int rt = tid >> 5, ct = tid & 31;
    float acc[8][8];
    #pragma unroll
    for (int i = 0; i < 8; i++)
        #pragma unroll
        for (int j = 0; j < 8; j++) acc[i][j] = sB3[ct*8 + j];
    #pragma unroll 2
    for (int k = 0; k < 128; k++) {
        float a[8], bb[8];
        #pragma unroll
        for (int i = 0; i < 8; i++) a[i] = sA[(rt*8+i)*132 + k];
        #pragma unroll
        for (int j = 0; j < 8; j++) bb[j] = sW3[k*256 + ct*8 + j];
        #pragma unroll
        for (int i = 0; i < 8; i++)
            #pragma unroll
            for (int j = 0; j < 8; j++) acc[i][j] = fmaf(a[i], bb[j], acc[i][j]);
    }
    float mx[8];
    #pragma unroll
    for (int j = 0; j < 8; j++) mx[j] = NEGB;
    #pragma unroll
    for (int i = 0; i < 8; i++)
        if (rt*8 + i < cnt)
            #pragma unroll
            for (int j = 0; j < 8; j++) mx[j] = fmaxf(mx[j], acc[i][j]);
    #pragma unroll
    for (int j = 0; j < 8; j++) sPart[rt*256 + ct*8 + j] = mx[j];
    __syncthreads();
    if (tid < 256) {
        float m = NEGB;
        #pragma unroll
        for (int r = 0; r < 8; r++) m = fmaxf(m, sPart[r*256 + tid]);
        g_x2cat[(size_t)q*259 + tid] = fmaxf(m, 0.f);
    }
}

// ----------------- generic tiled GEMM (unchanged) ----------------------------
__global__ void gemm_k(const float* __restrict__ A, const float* __restrict__ W,
                       const float* __restrict__ bias, float* __restrict__ C,
                       int M, int N, int K, int relu)
{
    __shared__ float As[16][132];
    __shared__ float Bs[16][64];
    int tid = threadIdx.x;
    int tr = tid >> 4, tc = tid & 15;
    int row0 = blockIdx.y * 128, col0 = blockIdx.x * 64;
    float acc[8][4];
    #pragma unroll
    for (int i = 0; i < 8; i++)
        #pragma unroll
        for (int j = 0; j < 4; j++) acc[i][j] = 0.f;
    for (int k0 = 0; k0 < K; k0 += 16) {
        #pragma unroll
        for (int l = 0; l < 8; l++) {
            int i = tid + l*256, r = i >> 4, c = i & 15;
            int gr = row0 + r, gc = k0 + c;
            As[c][r] = (gr < M && gc < K) ? A[(size_t)gr*K + gc] : 0.f;
        }
        #pragma unroll
        for (int l = 0; l < 4; l++) {
            int i = tid + l*256, r = i >> 6, c = i & 63;
            int gr = k0 + r, gc = col0 + c;
            Bs[r][c] = (gr < K && gc < N) ? W[(size_t)gr*N + gc] : 0.f;
        }
        __syncthreads();
        #pragma unroll
        for (int k = 0; k < 16; k++) {
            float a[8], bb[4];
            #pragma unroll
            for (int i = 0; i < 8; i++) a[i] = As[k][tr*8 + i];
            #pragma unroll
            for (int j = 0; j < 4; j++) bb[j] = Bs[k][tc*4 + j];
            #pragma unroll
            for (int i = 0; i < 8; i++)
                #pragma unroll
                for (int j = 0; j < 4; j++) acc[i][j] = fmaf(a[i], bb[j], acc[i][j]);
        }
        __syncthreads();
    }
    #pragma unroll
    for (int i = 0; i < 8; i++) {
        int gr = row0 + tr*8 + i;
        if (gr < M) {
            #pragma unroll
            for (int j = 0; j < 4; j++) {
                int gc = col0 + tc*4 + j;
                if (gc < N) {
                    float v = acc[i][j] + bias[gc];
                    if (relu) v = fmaxf(v, 0.f);
                    C[(size_t)gr*N + gc] = v;
                }
            }
        }
    }
}

__global__ void poscat_kernel()
{
    int t = blockIdx.x * 256 + threadIdx.x;
    if (t < 4096*3) {
        int q = t / 3, c = t % 3;
        g_x2cat[(size_t)q*259 + 256 + c] = g_pos2[t];
    }
}

__global__ void gmax_kernel()
{
    int j = blockIdx.x * 256 + threadIdx.x;
    int g = blockIdx.y;
    float m = NEGB;
    const float* base = g_g3 + (size_t)g*128*1024 + j;
    for (int i = 0; i < 128; i++) m = fmaxf(m, base[(size_t)i*1024]);
    g_gmx[(size_t)g*1024 + j] = m;
}

__global__ void final_kernel(float* __restrict__ out)
{
    __shared__ float sm[8][7];
    int t = threadIdx.x;
    if (t < 56) {
        int b = t / 7, c = t % 7;
        float s = g_f3[(b*4)*7+c] + g_f3[(b*4+1)*7+c] + g_f3[(b*4+2)*7+c] + g_f3[(b*4+3)*7+c];
        sm[b][c] = s * 0.25f;
    }
    __syncthreads();
    if (t < 8) {
        float q0 = sm[t][3], q1 = sm[t][4], q2 = sm[t][5], q3 = sm[t][6];
        float nrm = sqrtf(q0*q0 + q1*q1 + q2*q2 + q3*q3);
        float d = fmaxf(nrm, 1e-12f);
        out[t*7+0] = sm[t][0]; out[t*7+1] = sm[t][1]; out[t*7+2] = sm[t][2];
        out[t*7+3] = q0/d; out[t*7+4] = q1/d; out[t*7+5] = q2/d; out[t*7+6] = q3/d;
    }
}

// ----------------- launcher --------------------------------------------------
extern "C" void kernel_launch(void* const* d_in, const int* in_sizes, int n_in,
                              void* d_out, int out_size)
{
    const float* pts  = (const float*)d_in[0];
    const float *s1w1 = (const float*)d_in[1],  *s1b1 = (const float*)d_in[2];
    const float *s1w2 = (const float*)d_in[3],  *s1b2 = (const float*)d_in[4];
    const float *s1w3 = (const float*)d_in[5],  *s1b3 = (const float*)d_in[6];
    const float *s2w1 = (const float*)d_in[7],  *s2b1 = (const float*)d_in[8];
    const float *s2w2 = (const float*)d_in[9],  *s2b2 = (const float*)d_in[10];
    const float *s2w3 = (const float*)d_in[11], *s2b3 = (const float*)d_in[12];
    const float *gw1  = (const float*)d_in[13], *gb1  = (const float*)d_in[14];
    const float *gw2  = (const float*)d_in[15], *gb2  = (const float*)d_in[16];
    const float *gw3  = (const float*)d_in[17], *gb3  = (const float*)d_in[18];
    const float *l1w  = (const float*)d_in[19], *l1b  = (const float*)d_in[20];
    const float *l2w  = (const float*)d_in[21], *l2b  = (const float*)d_in[22];
    const float *l3w  = (const float*)d_in[23], *l3b  = (const float*)d_in[24];

    float *pool, *pos1, *pos2, *x2cat, *g1b, *g2b, *gmx, *f1, *f2;
    int *nidx1, *cnt1, *nidx2, *cnt2;
    cudaGetSymbolAddress((void**)&pool,  g_pool);
    cudaGetSymbolAddress((void**)&pos1,  g_pos1);
    cudaGetSymbolAddress((void**)&pos2,  g_pos2);
    cudaGetSymbolAddress((void**)&nidx1, g_nidx1);
    cudaGetSymbolAddress((void**)&cnt1,  g_cnt1);
    cudaGetSymbolAddress((void**)&nidx2, g_nidx2);
    cudaGetSymbolAddress((void**)&cnt2,  g_cnt2);
    cudaGetSymbolAddress((void**)&x2cat, g_x2cat);
    cudaGetSymbolAddress((void**)&g1b,   g_g1);
    cudaGetSymbolAddress((void**)&g2b,   g_g2);
    cudaGetSymbolAddress((void**)&gmx,   g_gmx);
    cudaGetSymbolAddress((void**)&f1,    g_f1);
    cudaGetSymbolAddress((void**)&f2,    g_f2);
    float* g3b; cudaGetSymbolAddress((void**)&g3b, g_g3);
    float* f3;  cudaGetSymbolAddress((void**)&f3,  g_f3);
    float* h2s2 = pool;

    static int attr_done = 0;
    if (!attr_done) {
        cudaFuncSetAttribute(fps_kernel<32>, cudaFuncAttributeMaxDynamicSharedMemorySize, 4096*12 + 64);
        cudaFuncSetAttribute(fps_kernel<16>, cudaFuncAttributeMaxDynamicSharedMemorySize, 2048*12 + 64);
        cudaFuncSetAttribute(s1_fused,  cudaFuncAttributeMaxDynamicSharedMemorySize, 89344);
        cudaFuncSetAttribute(s2a_fused, cudaFuncAttributeMaxDynamicSharedMemorySize, 201216);
        cudaFuncSetAttribute(s2b_fused, cudaFuncAttributeMaxDynamicSharedMemorySize, 174080);
        attr_done = 1;
    }

    float r2a = (float)(0.1*0.1), r2b = (float)(0.2*0.2);

    // ---- stage 1 ----
    fps_kernel<32><<<8, 128, 4096*12 + 64>>>(pts, pos1, 4096, 2048);
    radius_kernel<<<2048, 256>>>(pts, pos1, 4096, 2048, r2a, nidx1, cnt1);
    s1_fused<<<16384, 256, 89344>>>(pts, s1w1, s1b1, s1w2, s1b2, s1w3, s1b3);

    // ---- stage 2 ----
    fps_kernel<16><<<8, 128, 2048*12 + 64>>>(pos1, pos2, 2048, 512);
    radius_kernel<<<512, 256>>>(pos1, pos2, 2048, 512, r2b, nidx2, cnt2);
    s2a_fused<<<4096, 256, 201216>>>(s2w1, s2b1, s2w2, s2b2, h2s2);
    s2b_fused<<<4096, 256, 174080>>>(h2s2, s2w3, s2b3);
    poscat_kernel<<<48, 256>>>();

    // ---- global MLP + pooling + head ----
    gemm_k<<<dim3(4, 32), 256>>>(x2cat, gw1, gb1, g1b, 4096, 256, 259, 1);
    gemm_k<<<dim3(8, 32), 256>>>(g1b, gw2, gb2, g2b, 4096, 512, 256, 1);
    gemm_k<<<dim3(16, 32), 256>>>(g2b, gw3, gb3, g3b, 4096, 1024, 512, 0);
    gmax_kernel<<<dim3(4, 32), 256>>>();
    gemm_k<<<dim3(8, 1), 256>>>(gmx, l1w, l1b, f1, 32, 512, 1024, 1);
    gemm_k<<<dim3(4, 1), 256>>>(f1, l2w, l2b, f2, 32, 256, 512, 1);
    gemm_k<<<dim3(1, 1), 256>>>(f2, l3w, l3b, f3, 32, 7, 256, 0);
    final_kernel<<<1, 64>>>((float*)d_out);
}

// round 8
// speedup vs baseline: 1.4922x; 1.1366x over previous
#include <cuda_runtime.h>
#include <math.h>

#define NEGB -1.0e30f

// ----------------- scratch -----------------
__device__ float g_pool[67108864];
__device__ float g_pos1[8*2048*3];
__device__ float g_pos2[8*512*3];
__device__ int   g_nidx1[8*2048*64];
__device__ int   g_cnt1[8*2048];
__device__ int   g_nidx2[8*512*64];
__device__ int   g_cnt2[8*512];
__device__ float g_x1[8*2048*128];
__device__ float g_x2cat[8*512*259];
__device__ float g_g1[8*512*256];
__device__ float g_g2[8*512*512];
__device__ float g_g3[8*512*1024];
__device__ float g_gmx[32*1024];
__device__ float g_f1[32*512];
__device__ float g_f2[32*256];
__device__ float g_f3[32*7];

// ---- packed f32x2 helpers (exact per-lane IEEE f32 ops) ----
__device__ __forceinline__ unsigned long long pk2(float lo, float hi) {
    unsigned long long r; asm("mov.b64 %0, {%1, %2};" : "=l"(r) : "f"(lo), "f"(hi)); return r;
}
__device__ __forceinline__ void upk2(unsigned long long v, float& lo, float& hi) {
    asm("mov.b64 {%0, %1}, %2;" : "=f"(lo), "=f"(hi) : "l"(v));
}
__device__ __forceinline__ unsigned long long add2(unsigned long long a, unsigned long long b) {
    unsigned long long r; asm("add.rn.f32x2 %0, %1, %2;" : "=l"(r) : "l"(a), "l"(b)); return r;
}
__device__ __forceinline__ unsigned long long mul2(unsigned long long a, unsigned long long b) {
    unsigned long long r; asm("mul.rn.f32x2 %0, %1, %2;" : "=l"(r) : "l"(a), "l"(b)); return r;
}

// ----------------- FPS v4: 128 thr, packed-f32x2 distances, rescan argmax ----
template<int PT>
__global__ __launch_bounds__(128) void fps_kernel(const float* __restrict__ posIn,
                                                  float* __restrict__ posOut,
                                                  int N, int S)
{
    extern __shared__ float sm[];
    float* spx = sm;
    float* spy = sm + N;
    float* spz = sm + 2*N;
    unsigned long long* part = (unsigned long long*)(sm + 3*N);  // [2][4]

    int b = blockIdx.x, t = threadIdx.x;
    int lane = t & 31, warp = t >> 5;
    const float* p = posIn + (size_t)b*N*3;
    unsigned long long pxp[PT/2], pyp[PT/2], pzp[PT/2];
    float mind[PT];
    #pragma unroll
    for (int jj = 0; jj < PT/2; jj++) {
        int i0 = (2*jj)*128 + t, i1 = (2*jj+1)*128 + t;
        float x0 = p[3*i0], y0 = p[3*i0+1], z0 = p[3*i0+2];
        float x1 = p[3*i1], y1 = p[3*i1+1], z1 = p[3*i1+2];
        spx[i0] = x0; spy[i0] = y0; spz[i0] = z0;
        spx[i1] = x1; spy[i1] = y1; spz[i1] = z1;
        pxp[jj] = pk2(x0, x1); pyp[jj] = pk2(y0, y1); pzp[jj] = pk2(z0, z1);
        mind[2*jj] = 3.402823466e38f; mind[2*jj+1] = 3.402823466e38f;
    }
    if (t == 0) {
        float* o = posOut + (size_t)b*S*3;
        o[0] = p[0]; o[1] = p[1]; o[2] = p[2];
    }
    __syncthreads();
    int bidx = 0;
    for (int s = 1; s < S; s++) {
        float lx = spx[bidx], ly = spy[bidx], lz = spz[bidx];
        unsigned long long nx = pk2(-lx, -lx), ny = pk2(-ly, -ly), nz = pk2(-lz, -lz);
        float bv = NEGB;
        #pragma unroll
        for (int jj = 0; jj < PT/2; jj++) {
            unsigned long long dx = add2(pxp[jj], nx);
            unsigned long long dy = add2(pyp[jj], ny);
            unsigned long long dz = add2(pzp[jj], nz);
            unsigned long long d2 = add2(add2(mul2(dx,dx), mul2(dy,dy)), mul2(dz,dz));
            float dlo, dhi; upk2(d2, dlo, dhi);
            float m0 = fminf(mind[2*jj],   dlo); mind[2*jj]   = m0;
            float m1 = fminf(mind[2*jj+1], dhi); mind[2*jj+1] = m1;
            bv = fmaxf(fmaxf(bv, m0), m1);
        }
        unsigned vb = __float_as_uint(bv);
        unsigned vmax = __reduce_max_sync(0xffffffffu, vb);
        int cand = 0x7fffffff;
        if (vb == vmax) {
            #pragma unroll
            for (int j = PT-1; j >= 0; j--)
                if (__float_as_uint(mind[j]) == vmax) cand = j*128 + t;
        }
        int widx = __reduce_min_sync(0xffffffffu, cand);
        if (lane == 0)
            part[(s & 1)*4 + warp] =
                ((unsigned long long)vmax << 32) | (unsigned)(0xFFFFFFFFu - (unsigned)widx);
        __syncthreads();
        const unsigned long long* pp = part + (s & 1)*4;
        unsigned long long k0 = pp[0], k1 = pp[1], k2 = pp[2], k3 = pp[3];
        k0 = k0 > k1 ? k0 : k1;
        k2 = k2 > k3 ? k2 : k3;
        k0 = k0 > k2 ? k0 : k2;
        bidx = (int)(0xFFFFFFFFu - (unsigned)(k0 & 0xFFFFFFFFu));
        if (t == 0) {
            float* o = posOut + ((size_t)b*S + s)*3;
            o[0] = spx[bidx]; o[1] = spy[bidx]; o[2] = spz[bidx];
        }
    }
}

// ----------------- radius NN (unchanged, exact) -----------------
__global__ void radius_kernel(const float* __restrict__ posAll, const float* __restrict__ posQ,
                              int N, int M, float r2,
                              int* __restrict__ nidx, int* __restrict__ cnt)
{
    __shared__ unsigned long long cand[8][256];
    __shared__ int scnt[8];
    int warp = threadIdx.x >> 5, lane = threadIdx.x & 31;
    int q = blockIdx.x * 8 + warp;
    int b = q / M;
    if (lane == 0) scnt[warp] = 0;
    __syncwarp();
    const float* qp = posQ + (size_t)q*3;
    float qx = qp[0], qy = qp[1], qz = qp[2];
    const float* p = posAll + (size_t)b*N*3;
    for (int i = lane; i < N; i += 32) {
        float dx = __fsub_rn(qx, p[3*i]);
        float dy = __fsub_rn(qy, p[3*i+1]);
        float dz = __fsub_rn(qz, p[3*i+2]);
        float d2 = __fadd_rn(__fadd_rn(__fmul_rn(dx,dx), __fmul_rn(dy,dy)), __fmul_rn(dz,dz));
        if (d2 <= r2) {
            int pos = atomicAdd(&scnt[warp], 1);
            if (pos < 256)
                cand[warp][pos] = ((unsigned long long)__float_as_uint(d2) << 32) | (unsigned)i;
        }
    }
    __syncwarp();
    int c = scnt[warp]; if (c > 256) c = 256;
    int* out = nidx + (size_t)q*64;
    if (c <= 64) {
        for (int t = lane; t < c; t += 32) out[t] = (int)(cand[warp][t] & 0xffffffffu);
        if (lane == 0) cnt[q] = c;
    } else {
        int slots = (c + 31) >> 5;
        for (int sel = 0; sel < 64; sel++) {
            unsigned long long best = ~0ULL;
            for (int k = 0; k < slots; k++) {
                int j = lane + (k << 5);
                if (j < c) { unsigned long long v = cand[warp][j]; if (v < best) best = v; }
            }
            #pragma unroll
            for (int off = 16; off; off >>= 1) {
                unsigned long long o = __shfl_down_sync(0xffffffffu, best, off);
                if (o < best) best = o;
            }
            best = __shfl_sync(0xffffffffu, best, 0);
            if (lane == 0) out[sel] = (int)(best & 0xffffffffu);
            for (int k = 0; k < slots; k++) {
                int j = lane + (k << 5);
                if (j < c && cand[warp][j] == best) cand[warp][j] = ~0ULL;
            }
        }
        if (lane == 0) cnt[q] = 64;
    }
}

// ============ Stage-1 fused with warp-level row skipping =====================
__global__ __launch_bounds__(256) void s1_fused(const float* __restrict__ pts,
    const float* __restrict__ w1, const float* __restrict__ b1,
    const float* __restrict__ w2, const float* __restrict__ b2,
    const float* __restrict__ w3, const float* __restrict__ b3)
{
    extern __shared__ float sm[];
    float* sW1 = sm;               // 192
    float* sB1 = sW1 + 192;        // 64
    float* sW2 = sB1 + 64;         // 4096
    float* sB2 = sW2 + 4096;       // 64
    float* sW3 = sB2 + 64;         // 8192
    float* sB3 = sW3 + 8192;       // 128
    float* sRel= sB3 + 128;        // 256
    float* sH1 = sRel + 256;       // 64*65
    float* sH2 = sH1 + 4160;       // 64*65
    float* sPart = sH2 + 4160;     // 8*128

    int q = blockIdx.x;
    int b = q >> 11;
    int tid = threadIdx.x;
    int lane = tid & 31, rt = tid >> 5;  // warp id = row tile
    for (int i = tid; i < 192;  i += 256) sW1[i] = w1[i];
    for (int i = tid; i < 64;   i += 256) { sB1[i] = b1[i]; sB2[i] = b2[i]; }
    for (int i = tid; i < 4096; i += 256) sW2[i] = w2[i];
    for (int i = tid; i < 8192; i += 256) sW3[i] = w3[i];
    if (tid < 128) sB3[tid] = b3[tid];
    int cnt = g_cnt1[q];
    if (tid < 64) {
        int idx = (tid < cnt) ? g_nidx1[q*64 + tid] : 0;
        const float* sp = pts + ((size_t)b*4096 + idx)*3;
        const float* qp = g_pos1 + (size_t)q*3;
        sRel[tid*4+0] = sp[0] - qp[0];
        sRel[tid*4+1] = sp[1] - qp[1];
        sRel[tid*4+2] = sp[2] - qp[2];
    }
    __syncthreads();
    int active = (rt*8 < cnt);           // warp-uniform row-tile skip
    // layer1 (3->64, relu): warp rt rows rt*8..rt*8+7, lane covers 2 cols
    if (active) {
        #pragma unroll
        for (int i = 0; i < 8; i++) {
            int m = rt*8 + i;
            float rx = sRel[m*4], ry = sRel[m*4+1], rz = sRel[m*4+2];
            #pragma unroll
            for (int jj = 0; jj < 2; jj++) {
                int c = lane + jj*32;
                float v = fmaf(rz, sW1[128+c], fmaf(ry, sW1[64+c], fmaf(rx, sW1[c], sB1[c])));
                sH1[m*65 + c] = fmaxf(v, 0.f);
            }
        }
    }
    __syncthreads();
    // layer2 (64->64, relu): warp rt rows rt*8.., lane cols lane, lane+32
    if (active) {
        float acc[8][2];
        #pragma unroll
        for (int i = 0; i < 8; i++) { acc[i][0] = sB2[lane]; acc[i][1] = sB2[lane+32]; }
        #pragma unroll 4
        for (int k = 0; k < 64; k++) {
            float b0 = sW2[k*64 + lane], b1v = sW2[k*64 + lane + 32];
            #pragma unroll
            for (int i = 0; i < 8; i++) {
                float a = sH1[(rt*8+i)*65 + k];
                acc[i][0] = fmaf(a, b0, acc[i][0]);
                acc[i][1] = fmaf(a, b1v, acc[i][1]);
            }
        }
        #pragma unroll
        for (int i = 0; i < 8; i++) {
            sH2[(rt*8+i)*65 + lane]      = fmaxf(acc[i][0], 0.f);
            sH2[(rt*8+i)*65 + lane + 32] = fmaxf(acc[i][1], 0.f);
        }
    }
    __syncthreads();
    // layer3 (64->128) + masked row-max
    if (active) {
        float acc[8][4];
        #pragma unroll
        for (int i = 0; i < 8; i++)
            #pragma unroll
            for (int j = 0; j < 4; j++) acc[i][j] = sB3[lane + j*32];
        #pragma unroll 4
        for (int k = 0; k < 64; k++) {
            float bb[4];
            #pragma unroll
            for (int j = 0; j < 4; j++) bb[j] = sW3[k*128 + lane + j*32];
            #pragma unroll
            for (int i = 0; i < 8; i++) {
                float a = sH2[(rt*8+i)*65 + k];
                #pragma unroll
                for (int j = 0; j < 4; j++) acc[i][j] = fmaf(a, bb[j], acc[i][j]);
            }
        }
        float mx[4] = {NEGB, NEGB, NEGB, NEGB};
        int lim = cnt - rt*8; if (lim > 8) lim = 8;
        for (int i = 0; i < lim; i++)
            #pragma unroll
            for (int j = 0; j < 4; j++) mx[j] = fmaxf(mx[j], acc[i][j]);
        #pragma unroll
        for (int j = 0; j < 4; j++) sPart[rt*128 + lane + j*32] = mx[j];
    }
    __syncthreads();
    if (tid < 128) {
        int nw = (cnt + 7) >> 3;
        float m = NEGB;
        for (int r = 0; r < nw; r++) m = fmaxf(m, sPart[r*128 + tid]);
        g_x1[(size_t)q*128 + tid] = fmaxf(m, 0.f);
    }
}

// ============ Stage-2 part A (unchanged) ============
__global__ __launch_bounds__(256) void s2a_fused(
    const float* __restrict__ w1, const float* __restrict__ b1,
    const float* __restrict__ w2, const float* __restrict__ b2,
    float* __restrict__ h2out)
{
    extern __shared__ float sm[];
    float* sW1 = sm;
    float* sB1 = sW1 + 16768;
    float* sW2 = sB1 + 128;
    float* sB2 = sW2 + 16384;
    float* sA  = sB2 + 128;
    float* sH1 = sA + 8448;

    int q = blockIdx.x;
    int b = q >> 9;
    int tid = threadIdx.x;
    for (int i = tid; i < 16768; i += 256) sW1[i] = w1[i];
    for (int i = tid; i < 16384; i += 256) sW2[i] = w2[i];
    if (tid < 128) { sB1[tid] = b1[tid]; sB2[tid] = b2[tid]; }
    int cnt = g_cnt2[q];
    {
        int m = tid >> 2, l4 = tid & 3;
        int idx = (m < cnt) ? g_nidx2[q*64 + m] : 0;
        const float4* src = (const float4*)(g_x1 + ((size_t)b*2048 + idx)*128);
        #pragma unroll
        for (int j = 0; j < 8; j++)
            *((float4*)(sA + m*132 + l4*32 + j*4)) = src[l4*8 + j];
        if (l4 == 0) {
            const float* ps = g_pos1 + ((size_t)b*2048 + idx)*3;
            const float* pq = g_pos2 + (size_t)q*3;
            sA[m*132 + 128] = ps[0] - pq[0];
            sA[m*132 + 129] = ps[1] - pq[1];
            sA[m*132 + 130] = ps[2] - pq[2];
        }
    }
    __syncthreads();
    int rt = tid >> 5, ct = tid & 31;
    {
        float acc[8][4];
        #pragma unroll
        for (int i = 0; i < 8; i++)
            #pragma unroll
            for (int j = 0; j < 4; j++) acc[i][j] = sB1[ct*4 + j];
        #pragma unroll 4
        for (int k = 0; k < 131; k++) {
            float a[8], bb[4];
            #pragma unroll
            for (int i = 0; i < 8; i++) a[i] = sA[(rt*8+i)*132 + k];
            #pragma unroll
            for (int j = 0; j < 4; j++) bb[j] = sW1[k*128 + ct*4 + j];
            #pragma unroll
            for (int i = 0; i < 8; i++)
                #pragma unroll
                for (int j = 0; j < 4; j++) acc[i][j] = fmaf(a[i], bb[j], acc[i][j]);
        }
        #pragma unroll
        for (int i = 0; i < 8; i++)
            #pragma unroll
            for (int j = 0; j < 4; j++)
                sH1[(rt*8+i)*132 + ct*4 + j] = fmaxf(acc[i][j], 0.f);
    }
    __syncthreads();
    {
        float acc[8][4];
        #pragma unroll
        for (int i = 0; i < 8; i++)
            #pragma unroll
            for (int j = 0; j < 4; j++) acc[i][j] = sB2[ct*4 + j];
        #pragma unroll 4
        for (int k = 0; k < 128; k++) {
            float a[8], bb[4];
            #pragma unroll
            for (int i = 0; i < 8; i++) a[i] = sH1[(rt*8+i)*132 + k];
            #pragma unroll
            for (int j = 0; j < 4; j++) bb[j] = sW2[k*128 + ct*4 + j];
            #pragma unroll
            for (int i = 0; i < 8; i++)
                #pragma unroll
                for (int j = 0; j < 4; j++) acc[i][j] = fmaf(a[i], bb[j], acc[i][j]);
        }
        #pragma unroll
        for (int i = 0; i < 8; i++) {
            float4 v = make_float4(fmaxf(acc[i][0],0.f), fmaxf(acc[i][1],0.f),
                                   fmaxf(acc[i][2],0.f), fmaxf(acc[i][3],0.f));
            *((float4*)(h2out + ((size_t)q*64 + rt*8 + i)*128 + ct*4)) = v;
        }
    }
}

// ============ Stage-2 part B (unchanged) ============
__global__ __launch_bounds__(256) void s2b_fused(
    const float* __restrict__ h2, const float* __restrict__ w3, const float* __restrict__ b3)
{
    extern __shared__ float sm[];
    float* sW3 = sm;
    float* sB3 = sW3 + 32768;
    float* sA  = sB3 + 256;
    float* sPart = sA + 8448;

    int q = blockIdx.x;
    int tid = threadIdx.x;
    for (int i = tid; i < 32768; i += 256) sW3[i] = w3[i];
    if (tid < 256) sB3[tid] = b3[tid];
    {
        int m = tid >> 2, l4 = tid & 3;
        const float4* src = (const float4*)(h2 + ((size_t)q*64 + m)*128);
        #pragma unroll
        for (int j = 0; j < 8; j++)
            *((float4*)(sA + m*132 + l4*32 + j*4)) = src[l4*8 + j];
    }
    __syncthreads();
    int cnt = g_cnt2[q];
    int rt = tid >> 5, ct = tid & 31;
    float acc[8][8];
    #pragma unroll
    for (int i = 0; i < 8; i++)
        #pragma unroll
        for (int j = 0; j < 8; j++) acc[i][j] = sB3[ct*8 + j];
    #pragma unroll 2
    for (int k = 0; k < 128; k++) {
        float a[8], bb[8];
        #pragma unroll
        for (int i = 0; i < 8; i++) a[i] = sA[(rt*8+i)*132 + k];
        #pragma unroll
        for (int j = 0; j < 8; j++) bb[j] = sW3[k*256 + ct*8 + j];
        #pragma unroll
        for (int i = 0; i < 8; i++)
            #pragma unroll
            for (int j = 0; j < 8; j++) acc[i][j] = fmaf(a[i], bb[j], acc[i][j]);
    }
    float mx[8];
    #pragma unroll
    for (int j = 0; j < 8; j++) mx[j] = NEGB;
    #pragma unroll
    for (int i = 0; i < 8; i++)
        if (rt*8 + i < cnt)
            #pragma unroll
            for (int j = 0; j < 8; j++) mx[j] = fmaxf(mx[j], acc[i][j]);
    #pragma unroll
    for (int j = 0; j < 8; j++) sPart[rt*256 + ct*8 + j] = mx[j];
    __syncthreads();
    if (tid < 256) {
        float m = NEGB;
        #pragma unroll
        for (int r = 0; r < 8; r++) m = fmaxf(m, sPart[r*256 + tid]);
        g_x2cat[(size_t)q*259 + tid] = fmaxf(m, 0.f);
    }
}

// ----------------- generic tiled GEMM (unchanged) ----------------------------
__global__ void gemm_k(const float* __restrict__ A, const float* __restrict__ W,
                       const float* __restrict__ bias, float* __restrict__ C,
                       int M, int N, int K, int relu)
{
    __shared__ float As[16][132];
    __shared__ float Bs[16][64];
    int tid = threadIdx.x;
    int tr = tid >> 4, tc = tid & 15;
    int row0 = blockIdx.y * 128, col0 = blockIdx.x * 64;
    float acc[8][4];
    #pragma unroll
    for (int i = 0; i < 8; i++)
        #pragma unroll
        for (int j = 0; j < 4; j++) acc[i][j] = 0.f;
    for (int k0 = 0; k0 < K; k0 += 16) {
        #pragma unroll
        for (int l = 0; l < 8; l++) {
            int i = tid + l*256, r = i >> 4, c = i & 15;
            int gr = row0 + r, gc = k0 + c;
            As[c][r] = (gr < M && gc < K) ? A[(size_t)gr*K + gc] : 0.f;
        }
        #pragma unroll
        for (int l = 0; l < 4; l++) {
            int i = tid + l*256, r = i >> 6, c = i & 63;
            int gr = k0 + r, gc = col0 + c;
            Bs[r][c] = (gr < K && gc < N) ? W[(size_t)gr*N + gc] : 0.f;
        }
        __syncthreads();
        #pragma unroll
        for (int k = 0; k < 16; k++) {
            float a[8], bb[4];
            #pragma unroll
            for (int i = 0; i < 8; i++) a[i] = As[k][tr*8 + i];
            #pragma unroll
            for (int j = 0; j < 4; j++) bb[j] = Bs[k][tc*4 + j];
            #pragma unroll
            for (int i = 0; i < 8; i++)
                #pragma unroll
                for (int j = 0; j < 4; j++) acc[i][j] = fmaf(a[i], bb[j], acc[i][j]);
        }
        __syncthreads();
    }
    #pragma unroll
    for (int i = 0; i < 8; i++) {
        int gr = row0 + tr*8 + i;
        if (gr < M) {
            #pragma unroll
            for (int j = 0; j < 4; j++) {
                int gc = col0 + tc*4 + j;
                if (gc < N) {
                    float v = acc[i][j] + bias[gc];
                    if (relu) v = fmaxf(v, 0.f);
                    C[(size_t)gr*N + gc] = v;
                }
            }
        }
    }
}

__global__ void poscat_kernel()
{
    int t = blockIdx.x * 256 + threadIdx.x;
    if (t < 4096*3) {
        int q = t / 3, c = t % 3;
        g_x2cat[(size_t)q*259 + 256 + c] = g_pos2[t];
    }
}

__global__ void gmax_kernel()
{
    int j = blockIdx.x * 256 + threadIdx.x;
    int g = blockIdx.y;
    float m = NEGB;
    const float* base = g_g3 + (size_t)g*128*1024 + j;
    for (int i = 0; i < 128; i++) m = fmaxf(m, base[(size_t)i*1024]);
    g_gmx[(size_t)g*1024 + j] = m;
}

__global__ void final_kernel(float* __restrict__ out)
{
    __shared__ float sm[8][7];
    int t = threadIdx.x;
    if (t < 56) {
        int b = t / 7, c = t % 7;
        float s = g_f3[(b*4)*7+c] + g_f3[(b*4+1)*7+c] + g_f3[(b*4+2)*7+c] + g_f3[(b*4+3)*7+c];
        sm[b][c] = s * 0.25f;
    }
    __syncthreads();
    if (t < 8) {
        float q0 = sm[t][3], q1 = sm[t][4], q2 = sm[t][5], q3 = sm[t][6];
        float nrm = sqrtf(q0*q0 + q1*q1 + q2*q2 + q3*q3);
        float d = fmaxf(nrm, 1e-12f);
        out[t*7+0] = sm[t][0]; out[t*7+1] = sm[t][1]; out[t*7+2] = sm[t][2];
        out[t*7+3] = q0/d; out[t*7+4] = q1/d; out[t*7+5] = q2/d; out[t*7+6] = q3/d;
    }
}

// ----------------- launcher --------------------------------------------------
extern "C" void kernel_launch(void* const* d_in, const int* in_sizes, int n_in,
                              void* d_out, int out_size)
{
    const float* pts  = (const float*)d_in[0];
    const float *s1w1 = (const float*)d_in[1],  *s1b1 = (const float*)d_in[2];
    const float *s1w2 = (const float*)d_in[3],  *s1b2 = (const float*)d_in[4];
    const float *s1w3 = (const float*)d_in[5],  *s1b3 = (const float*)d_in[6];
    const float *s2w1 = (const float*)d_in[7],  *s2b1 = (const float*)d_in[8];
    const float *s2w2 = (const float*)d_in[9],  *s2b2 = (const float*)d_in[10];
    const float *s2w3 = (const float*)d_in[11], *s2b3 = (const float*)d_in[12];
    const float *gw1  = (const float*)d_in[13], *gb1  = (const float*)d_in[14];
    const float *gw2  = (const float*)d_in[15], *gb2  = (const float*)d_in[16];
    const float *gw3  = (const float*)d_in[17], *gb3  = (const float*)d_in[18];
    const float *l1w  = (const float*)d_in[19], *l1b  = (const float*)d_in[20];
    const float *l2w  = (const float*)d_in[21], *l2b  = (const float*)d_in[22];
    const float *l3w  = (const float*)d_in[23], *l3b  = (const float*)d_in[24];

    float *pool, *pos1, *pos2, *x2cat, *g1b, *g2b, *gmx, *f1, *f2;
    int *nidx1, *cnt1, *nidx2, *cnt2;
    cudaGetSymbolAddress((void**)&pool,  g_pool);
    cudaGetSymbolAddress((void**)&pos1,  g_pos1);
    cudaGetSymbolAddress((void**)&pos2,  g_pos2);
    cudaGetSymbolAddress((void**)&nidx1, g_nidx1);
    cudaGetSymbolAddress((void**)&cnt1,  g_cnt1);
    cudaGetSymbolAddress((void**)&nidx2, g_nidx2);
    cudaGetSymbolAddress((void**)&cnt2,  g_cnt2);
    cudaGetSymbolAddress((void**)&x2cat, g_x2cat);
    cudaGetSymbolAddress((void**)&g1b,   g_g1);
    cudaGetSymbolAddress((void**)&g2b,   g_g2);
    cudaGetSymbolAddress((void**)&gmx,   g_gmx);
    cudaGetSymbolAddress((void**)&f1,    g_f1);
    cudaGetSymbolAddress((void**)&f2,    g_f2);
    float* g3b; cudaGetSymbolAddress((void**)&g3b, g_g3);
    float* f3;  cudaGetSymbolAddress((void**)&f3,  g_f3);
    float* h2s2 = pool;

    static int attr_done = 0;
    if (!attr_done) {
        cudaFuncSetAttribute(fps_kernel<32>, cudaFuncAttributeMaxDynamicSharedMemorySize, 4096*12 + 64);
        cudaFuncSetAttribute(fps_kernel<16>, cudaFuncAttributeMaxDynamicSharedMemorySize, 2048*12 + 64);
        cudaFuncSetAttribute(s1_fused,  cudaFuncAttributeMaxDynamicSharedMemorySize, 89344);
        cudaFuncSetAttribute(s2a_fused, cudaFuncAttributeMaxDynamicSharedMemorySize, 201216);
        cudaFuncSetAttribute(s2b_fused, cudaFuncAttributeMaxDynamicSharedMemorySize, 174080);
        attr_done = 1;
    }

    float r2a = (float)(0.1*0.1), r2b = (float)(0.2*0.2);

    // ---- stage 1 ----
    fps_kernel<32><<<8, 128, 4096*12 + 64>>>(pts, pos1, 4096, 2048);
    radius_kernel<<<2048, 256>>>(pts, pos1, 4096, 2048, r2a, nidx1, cnt1);
    s1_fused<<<16384, 256, 89344>>>(pts, s1w1, s1b1, s1w2, s1b2, s1w3, s1b3);

    // ---- stage 2 ----
    fps_kernel<16><<<8, 128, 2048*12 + 64>>>(pos1, pos2, 2048, 512);
    radius_kernel<<<512, 256>>>(pos1, pos2, 2048, 512, r2b, nidx2, cnt2);
    s2a_fused<<<4096, 256, 201216>>>(s2w1, s2b1, s2w2, s2b2, h2s2);
    s2b_fused<<<4096, 256, 174080>>>(h2s2, s2w3, s2b3);
    poscat_kernel<<<48, 256>>>();

    // ---- global MLP + pooling + head ----
    gemm_k<<<dim3(4, 32), 256>>>(x2cat, gw1, gb1, g1b, 4096, 256, 259, 1);
    gemm_k<<<dim3(8, 32), 256>>>(g1b, gw2, gb2, g2b, 4096, 512, 256, 1);
    gemm_k<<<dim3(16, 32), 256>>>(g2b, gw3, gb3, g3b, 4096, 1024, 512, 0);
    gmax_kernel<<<dim3(4, 32), 256>>>();
    gemm_k<<<dim3(8, 1), 256>>>(gmx, l1w, l1b, f1, 32, 512, 1024, 1);
    gemm_k<<<dim3(4, 1), 256>>>(f1, l2w, l2b, f2, 32, 256, 512, 1);
    gemm_k<<<dim3(1, 1), 256>>>(f2, l3w, l3b, f3, 32, 7, 256, 0);
    final_kernel<<<1, 64>>>((float*)d_out);
}

// round 9
// speedup vs baseline: 1.7204x; 1.1529x over previous
#include <cuda_runtime.h>
#include <math.h>

#define NEGB -1.0e30f

// ----------------- scratch -----------------
__device__ float g_pool[67108864];
__device__ float g_pos1[8*2048*3];
__device__ float g_pos2[8*512*3];
__device__ int   g_nidx1[8*2048*64];
__device__ int   g_cnt1[8*2048];
__device__ int   g_nidx2[8*512*64];
__device__ int   g_cnt2[8*512];
__device__ float g_x1[8*2048*128];
__device__ float g_x2cat[8*512*259];
__device__ float g_g1[8*512*256];
__device__ float g_g2[8*512*512];
__device__ float g_g3[8*512*1024];
__device__ float g_gmx[32*1024];
__device__ float g_f1[32*512];
__device__ float g_f2[32*256];
__device__ float g_f3[32*7];

// ---- packed f32x2 helpers (exact per-lane IEEE f32 ops) ----
__device__ __forceinline__ unsigned long long pk2(float lo, float hi) {
    unsigned long long r; asm("mov.b64 %0, {%1, %2};" : "=l"(r) : "f"(lo), "f"(hi)); return r;
}
__device__ __forceinline__ void upk2(unsigned long long v, float& lo, float& hi) {
    asm("mov.b64 {%0, %1}, %2;" : "=f"(lo), "=f"(hi) : "l"(v));
}
__device__ __forceinline__ unsigned long long add2(unsigned long long a, unsigned long long b) {
    unsigned long long r; asm("add.rn.f32x2 %0, %1, %2;" : "=l"(r) : "l"(a), "l"(b)); return r;
}
__device__ __forceinline__ unsigned long long mul2(unsigned long long a, unsigned long long b) {
    unsigned long long r; asm("mul.rn.f32x2 %0, %1, %2;" : "=l"(r) : "l"(a), "l"(b)); return r;
}

// ----------------- FPS v4 (unchanged from R8) -----------------
template<int PT>
__global__ __launch_bounds__(128) void fps_kernel(const float* __restrict__ posIn,
                                                  float* __restrict__ posOut,
                                                  int N, int S)
{
    extern __shared__ float sm[];
    float* spx = sm;
    float* spy = sm + N;
    float* spz = sm + 2*N;
    unsigned long long* part = (unsigned long long*)(sm + 3*N);

    int b = blockIdx.x, t = threadIdx.x;
    int lane = t & 31, warp = t >> 5;
    const float* p = posIn + (size_t)b*N*3;
    unsigned long long pxp[PT/2], pyp[PT/2], pzp[PT/2];
    float mind[PT];
    #pragma unroll
    for (int jj = 0; jj < PT/2; jj++) {
        int i0 = (2*jj)*128 + t, i1 = (2*jj+1)*128 + t;
        float x0 = p[3*i0], y0 = p[3*i0+1], z0 = p[3*i0+2];
        float x1 = p[3*i1], y1 = p[3*i1+1], z1 = p[3*i1+2];
        spx[i0] = x0; spy[i0] = y0; spz[i0] = z0;
        spx[i1] = x1; spy[i1] = y1; spz[i1] = z1;
        pxp[jj] = pk2(x0, x1); pyp[jj] = pk2(y0, y1); pzp[jj] = pk2(z0, z1);
        mind[2*jj] = 3.402823466e38f; mind[2*jj+1] = 3.402823466e38f;
    }
    if (t == 0) {
        float* o = posOut + (size_t)b*S*3;
        o[0] = p[0]; o[1] = p[1]; o[2] = p[2];
    }
    __syncthreads();
    int bidx = 0;
    for (int s = 1; s < S; s++) {
        float lx = spx[bidx], ly = spy[bidx], lz = spz[bidx];
        unsigned long long nx = pk2(-lx, -lx), ny = pk2(-ly, -ly), nz = pk2(-lz, -lz);
        float bv = NEGB;
        #pragma unroll
        for (int jj = 0; jj < PT/2; jj++) {
            unsigned long long dx = add2(pxp[jj], nx);
            unsigned long long dy = add2(pyp[jj], ny);
            unsigned long long dz = add2(pzp[jj], nz);
            unsigned long long d2 = add2(add2(mul2(dx,dx), mul2(dy,dy)), mul2(dz,dz));
            float dlo, dhi; upk2(d2, dlo, dhi);
            float m0 = fminf(mind[2*jj],   dlo); mind[2*jj]   = m0;
            float m1 = fminf(mind[2*jj+1], dhi); mind[2*jj+1] = m1;
            bv = fmaxf(fmaxf(bv, m0), m1);
        }
        unsigned vb = __float_as_uint(bv);
        unsigned vmax = __reduce_max_sync(0xffffffffu, vb);
        int cand = 0x7fffffff;
        if (vb == vmax) {
            #pragma unroll
            for (int j = PT-1; j >= 0; j--)
                if (__float_as_uint(mind[j]) == vmax) cand = j*128 + t;
        }
        int widx = __reduce_min_sync(0xffffffffu, cand);
        if (lane == 0)
            part[(s & 1)*4 + warp] =
                ((unsigned long long)vmax << 32) | (unsigned)(0xFFFFFFFFu - (unsigned)widx);
        __syncthreads();
        const unsigned long long* pp = part + (s & 1)*4;
        unsigned long long k0 = pp[0], k1 = pp[1], k2 = pp[2], k3 = pp[3];
        k0 = k0 > k1 ? k0 : k1;
        k2 = k2 > k3 ? k2 : k3;
        k0 = k0 > k2 ? k0 : k2;
        bidx = (int)(0xFFFFFFFFu - (unsigned)(k0 & 0xFFFFFFFFu));
        if (t == 0) {
            float* o = posOut + ((size_t)b*S + s)*3;
            o[0] = spx[bidx]; o[1] = spy[bidx]; o[2] = spz[bidx];
        }
    }
}

// ----------------- radius NN (unchanged, exact) -----------------
__global__ void radius_kernel(const float* __restrict__ posAll, const float* __restrict__ posQ,
                              int N, int M, float r2,
                              int* __restrict__ nidx, int* __restrict__ cnt)
{
    __shared__ unsigned long long cand[8][256];
    __shared__ int scnt[8];
    int warp = threadIdx.x >> 5, lane = threadIdx.x & 31;
    int q = blockIdx.x * 8 + warp;
    int b = q / M;
    if (lane == 0) scnt[warp] = 0;
    __syncwarp();
    const float* qp = posQ + (size_t)q*3;
    float qx = qp[0], qy = qp[1], qz = qp[2];
    const float* p = posAll + (size_t)b*N*3;
    for (int i = lane; i < N; i += 32) {
        float dx = __fsub_rn(qx, p[3*i]);
        float dy = __fsub_rn(qy, p[3*i+1]);
        float dz = __fsub_rn(qz, p[3*i+2]);
        float d2 = __fadd_rn(__fadd_rn(__fmul_rn(dx,dx), __fmul_rn(dy,dy)), __fmul_rn(dz,dz));
        if (d2 <= r2) {
            int pos = atomicAdd(&scnt[warp], 1);
            if (pos < 256)
                cand[warp][pos] = ((unsigned long long)__float_as_uint(d2) << 32) | (unsigned)i;
        }
    }
    __syncwarp();
    int c = scnt[warp]; if (c > 256) c = 256;
    int* out = nidx + (size_t)q*64;
    if (c <= 64) {
        for (int t = lane; t < c; t += 32) out[t] = (int)(cand[warp][t] & 0xffffffffu);
        if (lane == 0) cnt[q] = c;
    } else {
        int slots = (c + 31) >> 5;
        for (int sel = 0; sel < 64; sel++) {
            unsigned long long best = ~0ULL;
            for (int k = 0; k < slots; k++) {
                int j = lane + (k << 5);
                if (j < c) { unsigned long long v = cand[warp][j]; if (v < best) best = v; }
            }
            #pragma unroll
            for (int off = 16; off; off >>= 1) {
                unsigned long long o = __shfl_down_sync(0xffffffffu, best, off);
                if (o < best) best = o;
            }
            best = __shfl_sync(0xffffffffu, best, 0);
            if (lane == 0) out[sel] = (int)(best & 0xffffffffu);
            for (int k = 0; k < slots; k++) {
                int j = lane + (k << 5);
                if (j < c && cand[warp][j] == best) cand[warp][j] = ~0ULL;
            }
        }
        if (lane == 0) cnt[q] = 64;
    }
}

// ============ Stage-1 fused, 4 queries per block =============================
__global__ __launch_bounds__(256) void s1_fused(const float* __restrict__ pts,
    const float* __restrict__ w1, const float* __restrict__ b1,
    const float* __restrict__ w2, const float* __restrict__ b2,
    const float* __restrict__ w3, const float* __restrict__ b3)
{
    extern __shared__ float sm[];
    float* sW1 = sm;
    float* sB1 = sW1 + 192;
    float* sW2 = sB1 + 64;
    float* sB2 = sW2 + 4096;
    float* sW3 = sB2 + 64;
    float* sB3 = sW3 + 8192;
    float* sRel= sB3 + 128;
    float* sH1 = sRel + 256;
    float* sH2 = sH1 + 4160;
    float* sPart = sH2 + 4160;

    int tid = threadIdx.x;
    int lane = tid & 31, rt = tid >> 5;
    for (int i = tid; i < 192;  i += 256) sW1[i] = w1[i];
    for (int i = tid; i < 64;   i += 256) { sB1[i] = b1[i]; sB2[i] = b2[i]; }
    for (int i = tid; i < 4096; i += 256) sW2[i] = w2[i];
    for (int i = tid; i < 8192; i += 256) sW3[i] = w3[i];
    if (tid < 128) sB3[tid] = b3[tid];

    for (int qi = 0; qi < 4; qi++) {
        int q = blockIdx.x*4 + qi;
        int b = q >> 11;
        int cnt = g_cnt1[q];
        if (tid < 64) {
            int idx = (tid < cnt) ? g_nidx1[q*64 + tid] : 0;
            const float* sp = pts + ((size_t)b*4096 + idx)*3;
            const float* qp = g_pos1 + (size_t)q*3;
            sRel[tid*4+0] = sp[0] - qp[0];
            sRel[tid*4+1] = sp[1] - qp[1];
            sRel[tid*4+2] = sp[2] - qp[2];
        }
        __syncthreads();
        int active = (rt*8 < cnt);
        if (active) {
            #pragma unroll
            for (int i = 0; i < 8; i++) {
                int m = rt*8 + i;
                float rx = sRel[m*4], ry = sRel[m*4+1], rz = sRel[m*4+2];
                #pragma unroll
                for (int jj = 0; jj < 2; jj++) {
                    int c = lane + jj*32;
                    float v = fmaf(rz, sW1[128+c], fmaf(ry, sW1[64+c], fmaf(rx, sW1[c], sB1[c])));
                    sH1[m*65 + c] = fmaxf(v, 0.f);
                }
            }
        }
        __syncthreads();
        if (active) {
            float acc[8][2];
            #pragma unroll
            for (int i = 0; i < 8; i++) { acc[i][0] = sB2[lane]; acc[i][1] = sB2[lane+32]; }
            #pragma unroll 4
            for (int k = 0; k < 64; k++) {
                float b0 = sW2[k*64 + lane], b1v = sW2[k*64 + lane + 32];
                #pragma unroll
                for (int i = 0; i < 8; i++) {
                    float a = sH1[(rt*8+i)*65 + k];
                    acc[i][0] = fmaf(a, b0, acc[i][0]);
                    acc[i][1] = fmaf(a, b1v, acc[i][1]);
                }
            }
            #pragma unroll
            for (int i = 0; i < 8; i++) {
                sH2[(rt*8+i)*65 + lane]      = fmaxf(acc[i][0], 0.f);
                sH2[(rt*8+i)*65 + lane + 32] = fmaxf(acc[i][1], 0.f);
            }
        }
        __syncthreads();
        if (active) {
            float acc[8][4];
            #pragma unroll
            for (int i = 0; i < 8; i++)
                #pragma unroll
                for (int j = 0; j < 4; j++) acc[i][j] = sB3[lane + j*32];
            #pragma unroll 4
            for (int k = 0; k < 64; k++) {
                float bb[4];
                #pragma unroll
                for (int j = 0; j < 4; j++) bb[j] = sW3[k*128 + lane + j*32];
                #pragma unroll
                for (int i = 0; i < 8; i++) {
                    float a = sH2[(rt*8+i)*65 + k];
                    #pragma unroll
                    for (int j = 0; j < 4; j++) acc[i][j] = fmaf(a, bb[j], acc[i][j]);
                }
            }
            float mx[4] = {NEGB, NEGB, NEGB, NEGB};
            int lim = cnt - rt*8; if (lim > 8) lim = 8;
            for (int i = 0; i < lim; i++)
                #pragma unroll
                for (int j = 0; j < 4; j++) mx[j] = fmaxf(mx[j], acc[i][j]);
            #pragma unroll
            for (int j = 0; j < 4; j++) sPart[rt*128 + lane + j*32] = mx[j];
        }
        __syncthreads();
        if (tid < 128) {
            int nw = (cnt + 7) >> 3;
            float m = NEGB;
            for (int r = 0; r < nw; r++) m = fmaxf(m, sPart[r*128 + tid]);
            g_x1[(size_t)q*128 + tid] = fmaxf(m, 0.f);
        }
        __syncthreads();
    }
}

// ============ Stage-2 part A, 4 queries per block ============================
__global__ __launch_bounds__(256) void s2a_fused(
    const float* __restrict__ w1, const float* __restrict__ b1,
    const float* __restrict__ w2, const float* __restrict__ b2,
    float* __restrict__ h2out)
{
    extern __shared__ float sm[];
    float* sW1 = sm;
    float* sB1 = sW1 + 16768;
    float* sW2 = sB1 + 128;
    float* sB2 = sW2 + 16384;
    float* sA  = sB2 + 128;
    float* sH1 = sA + 8448;

    int tid = threadIdx.x;
    for (int i = tid; i < 16768; i += 256) sW1[i] = w1[i];
    for (int i = tid; i < 16384; i += 256) sW2[i] = w2[i];
    if (tid < 128) { sB1[tid] = b1[tid]; sB2[tid] = b2[tid]; }
    int rt = tid >> 5, ct = tid & 31;

    for (int qi = 0; qi < 4; qi++) {
        int q = blockIdx.x*4 + qi;
        int b = q >> 9;
        int cnt = g_cnt2[q];
        {
            int m = tid >> 2, l4 = tid & 3;
            int idx = (m < cnt) ? g_nidx2[q*64 + m] : 0;
            const float4* src = (const float4*)(g_x1 + ((size_t)b*2048 + idx)*128);
            #pragma unroll
            for (int j = 0; j < 8; j++)
                *((float4*)(sA + m*132 + l4*32 + j*4)) = src[l4*8 + j];
            if (l4 == 0) {
                const float* ps = g_pos1 + ((size_t)b*2048 + idx)*3;
                const float* pq = g_pos2 + (size_t)q*3;
                sA[m*132 + 128] = ps[0] - pq[0];
                sA[m*132 + 129] = ps[1] - pq[1];
                sA[m*132 + 130] = ps[2] - pq[2];
            }
        }
        __syncthreads();
        {
            float acc[8][4];
            #pragma unroll
            for (int i = 0; i < 8; i++)
                #pragma unroll
                for (int j = 0; j < 4; j++) acc[i][j] = sB1[ct*4 + j];
            #pragma unroll 4
            for (int k = 0; k < 131; k++) {
                float a[8], bb[4];
                #pragma unroll
                for (int i = 0; i < 8; i++) a[i] = sA[(rt*8+i)*132 + k];
                #pragma unroll
                for (int j = 0; j < 4; j++) bb[j] = sW1[k*128 + ct*4 + j];
                #pragma unroll
                for (int i = 0; i < 8; i++)
                    #pragma unroll
                    for (int j = 0; j < 4; j++) acc[i][j] = fmaf(a[i], bb[j], acc[i][j]);
            }
            __syncthreads();
            #pragma unroll
            for (int i = 0; i < 8; i++)
                #pragma unroll
                for (int j = 0; j < 4; j++)
                    sH1[(rt*8+i)*132 + ct*4 + j] = fmaxf(acc[i][j], 0.f);
        }
        __syncthreads();
        {
            float acc[8][4];
            #pragma unroll
            for (int i = 0; i < 8; i++)
                #pragma unroll
                for (int j = 0; j < 4; j++) acc[i][j] = sB2[ct*4 + j];
            #pragma unroll 4
            for (int k = 0; k < 128; k++) {
                float a[8], bb[4];
                #pragma unroll
                for (int i = 0; i < 8; i++) a[i] = sH1[(rt*8+i)*132 + k];
                #pragma unroll
                for (int j = 0; j < 4; j++) bb[j] = sW2[k*128 + ct*4 + j];
                #pragma unroll
                for (int i = 0; i < 8; i++)
                    #pragma unroll
                    for (int j = 0; j < 4; j++) acc[i][j] = fmaf(a[i], bb[j], acc[i][j]);
            }
            #pragma unroll
            for (int i = 0; i < 8; i++) {
                float4 v = make_float4(fmaxf(acc[i][0],0.f), fmaxf(acc[i][1],0.f),
                                       fmaxf(acc[i][2],0.f), fmaxf(acc[i][3],0.f));
                *((float4*)(h2out + ((size_t)q*64 + rt*8 + i)*128 + ct*4)) = v;
            }
        }
        __syncthreads();
    }
}

// ============ Stage-2 part B, 4 queries per block ============================
__global__ __launch_bounds__(256) void s2b_fused(
    const float* __restrict__ h2, const float* __restrict__ w3, const float* __restrict__ b3)
{
    extern __shared__ float sm[];
    float* sW3 = sm;
    float* sB3 = sW3 + 32768;
    float* sA  = sB3 + 256;
    float* sPart = sA + 8448;

    int tid = threadIdx.x;
    for (int i = tid; i < 32768; i += 256) sW3[i] = w3[i];
    if (tid < 256) sB3[tid] = b3[tid];
    int rt = tid >> 5, ct = tid & 31;

    for (int qi = 0; qi < 4; qi++) {
        int q = blockIdx.x*4 + qi;
        {
            int m = tid >> 2, l4 = tid & 3;
            const float4* src = (const float4*)(h2 + ((size_t)q*64 + m)*128);
            #pragma unroll
            for (int j = 0; j < 8; j++)
                *((float4*)(sA + m*132 + l4*32 + j*4)) = src[l4*8 + j];
        }
        __syncthreads();
        int cnt = g_cnt2[q];
        float acc[8][8];
        #pragma unroll
        for (int i = 0; i < 8; i++)
            #pragma unroll
            for (int j = 0; j < 8; j++) acc[i][j] = sB3[ct*8 + j];
        #pragma unroll 2
        for (int k = 0; k < 128; k++) {
            float a[8], bb[8];
            #pragma unroll
            for (int i = 0; i < 8; i++) a[i] = sA[(rt*8+i)*132 + k];
            #pragma unroll
            for (int j = 0; j < 8; j++) bb[j] = sW3[k*256 + ct*8 + j];
            #pragma unroll
            for (int i = 0; i < 8; i++)
                #pragma unroll
                for (int j = 0; j < 8; j++) acc[i][j] = fmaf(a[i], bb[j], acc[i][j]);
        }
        float mx[8];
        #pragma unroll
        for (int j = 0; j < 8; j++) mx[j] = NEGB;
        #pragma unroll
        for (int i = 0; i < 8; i++)
            if (rt*8 + i < cnt)
                #pragma unroll
                for (int j = 0; j < 8; j++) mx[j] = fmaxf(mx[j], acc[i][j]);
        #pragma unroll
        for (int j = 0; j < 8; j++) sPart[rt*256 + ct*8 + j] = mx[j];
        __syncthreads();
        if (tid < 256) {
            float m = NEGB;
            #pragma unroll
            for (int r = 0; r < 8; r++) m = fmaxf(m, sPart[r*256 + tid]);
            g_x2cat[(size_t)q*259 + tid] = fmaxf(m, 0.f);
        }
        __syncthreads();
    }
}

// ----------------- generic tiled GEMM (unchanged) ----------------------------
__global__ void gemm_k(const float* __restrict__ A, const float* __restrict__ W,
                       const float* __restrict__ bias, float* __restrict__ C,
                       int M, int N, int K, int relu)
{
    __shared__ float As[16][132];
    __shared__ float Bs[16][64];
    int tid = threadIdx.x;
    int tr = tid >> 4, tc = tid & 15;
    int row0 = blockIdx.y * 128, col0 = blockIdx.x * 64;
    float acc[8][4];
    #pragma unroll
    for (int i = 0; i < 8; i++)
        #pragma unroll
        for (int j = 0; j < 4; j++) acc[i][j] = 0.f;
    for (int k0 = 0; k0 < K; k0 += 16) {
        #pragma unroll
        for (int l = 0; l < 8; l++) {
            int i = tid + l*256, r = i >> 4, c = i & 15;
            int gr = row0 + r, gc = k0 + c;
            As[c][r] = (gr < M && gc < K) ? A[(size_t)gr*K + gc] : 0.f;
        }
        #pragma unroll
        for (int l = 0; l < 4; l++) {
            int i = tid + l*256, r = i >> 6, c = i & 63;
            int gr = k0 + r, gc = col0 + c;
            Bs[r][c] = (gr < K && gc < N) ? W[(size_t)gr*N + gc] : 0.f;
        }
        __syncthreads();
        #pragma unroll
        for (int k = 0; k < 16; k++) {
            float a[8], bb[4];
            #pragma unroll
            for (int i = 0; i < 8; i++) a[i] = As[k][tr*8 + i];
            #pragma unroll
            for (int j = 0; j < 4; j++) bb[j] = Bs[k][tc*4 + j];
            #pragma unroll
            for (int i = 0; i < 8; i++)
                #pragma unroll
                for (int j = 0; j < 4; j++) acc[i][j] = fmaf(a[i], bb[j], acc[i][j]);
        }
        __syncthreads();
    }
    #pragma unroll
    for (int i = 0; i < 8; i++) {
        int gr = row0 + tr*8 + i;
        if (gr < M) {
            #pragma unroll
            for (int j = 0; j < 4; j++) {
                int gc = col0 + tc*4 + j;
                if (gc < N) {
                    float v = acc[i][j] + bias[gc];
                    if (relu) v = fmaxf(v, 0.f);
                    C[(size_t)gr*N + gc] = v;
                }
            }
        }
    }
}

__global__ void poscat_kernel()
{
    int t = blockIdx.x * 256 + threadIdx.x;
    if (t < 4096*3) {
        int q = t / 3, c = t % 3;
        g_x2cat[(size_t)q*259 + 256 + c] = g_pos2[t];
    }
}

__global__ void gmax_kernel()
{
    int j = blockIdx.x * 256 + threadIdx.x;
    int g = blockIdx.y;
    float m = NEGB;
    const float* base = g_g3 + (size_t)g*128*1024 + j;
    for (int i = 0; i < 128; i++) m = fmaxf(m, base[(size_t)i*1024]);
    g_gmx[(size_t)g*1024 + j] = m;
}

__global__ void final_kernel(float* __restrict__ out)
{
    __shared__ float sm[8][7];
    int t = threadIdx.x;
    if (t < 56) {
        int b = t / 7, c = t % 7;
        float s = g_f3[(b*4)*7+c] + g_f3[(b*4+1)*7+c] + g_f3[(b*4+2)*7+c] + g_f3[(b*4+3)*7+c];
        sm[b][c] = s * 0.25f;
    }
    __syncthreads();
    if (t < 8) {
        float q0 = sm[t][3], q1 = sm[t][4], q2 = sm[t][5], q3 = sm[t][6];
        float nrm = sqrtf(q0*q0 + q1*q1 + q2*q2 + q3*q3);
        float d = fmaxf(nrm, 1e-12f);
        out[t*7+0] = sm[t][0]; out[t*7+1] = sm[t][1]; out[t*7+2] = sm[t][2];
        out[t*7+3] = q0/d; out[t*7+4] = q1/d; out[t*7+5] = q2/d; out[t*7+6] = q3/d;
    }
}

// ----------------- launcher --------------------------------------------------
extern "C" void kernel_launch(void* const* d_in, const int* in_sizes, int n_in,
                              void* d_out, int out_size)
{
    const float* pts  = (const float*)d_in[0];
    const float *s1w1 = (const float*)d_in[1],  *s1b1 = (const float*)d_in[2];
    const float *s1w2 = (const float*)d_in[3],  *s1b2 = (const float*)d_in[4];
    const float *s1w3 = (const float*)d_in[5],  *s1b3 = (const float*)d_in[6];
    const float *s2w1 = (const float*)d_in[7],  *s2b1 = (const float*)d_in[8];
    const float *s2w2 = (const float*)d_in[9],  *s2b2 = (const float*)d_in[10];
    const float *s2w3 = (const float*)d_in[11], *s2b3 = (const float*)d_in[12];
    const float *gw1  = (const float*)d_in[13], *gb1  = (const float*)d_in[14];
    const float *gw2  = (const float*)d_in[15], *gb2  = (const float*)d_in[16];
    const float *gw3  = (const float*)d_in[17], *gb3  = (const float*)d_in[18];
    const float *l1w  = (const float*)d_in[19], *l1b  = (const float*)d_in[20];
    const float *l2w  = (const float*)d_in[21], *l2b  = (const float*)d_in[22];
    const float *l3w  = (const float*)d_in[23], *l3b  = (const float*)d_in[24];

    float *pool, *pos1, *pos2, *x2cat, *g1b, *g2b, *gmx, *f1, *f2;
    int *nidx1, *cnt1, *nidx2, *cnt2;
    cudaGetSymbolAddress((void**)&pool,  g_pool);
    cudaGetSymbolAddress((void**)&pos1,  g_pos1);
    cudaGetSymbolAddress((void**)&pos2,  g_pos2);
    cudaGetSymbolAddress((void**)&nidx1, g_nidx1);
    cudaGetSymbolAddress((void**)&cnt1,  g_cnt1);
    cudaGetSymbolAddress((void**)&nidx2, g_nidx2);
    cudaGetSymbolAddress((void**)&cnt2,  g_cnt2);
    cudaGetSymbolAddress((void**)&x2cat, g_x2cat);
    cudaGetSymbolAddress((void**)&g1b,   g_g1);
    cudaGetSymbolAddress((void**)&g2b,   g_g2);
    cudaGetSymbolAddress((void**)&gmx,   g_gmx);
    cudaGetSymbolAddress((void**)&f1,    g_f1);
    cudaGetSymbolAddress((void**)&f2,    g_f2);
    float* g3b; cudaGetSymbolAddress((void**)&g3b, g_g3);
    float* f3;  cudaGetSymbolAddress((void**)&f3,  g_f3);
    float* h2s2 = pool;

    static cudaStream_t sideStream = 0;
    static cudaEvent_t evPos1 = 0, evSide = 0;
    static int attr_done = 0;
    if (!attr_done) {
        cudaFuncSetAttribute(fps_kernel<32>, cudaFuncAttributeMaxDynamicSharedMemorySize, 4096*12 + 64);
        cudaFuncSetAttribute(fps_kernel<16>, cudaFuncAttributeMaxDynamicSharedMemorySize, 2048*12 + 64);
        cudaFuncSetAttribute(s1_fused,  cudaFuncAttributeMaxDynamicSharedMemorySize, 89344);
        cudaFuncSetAttribute(s2a_fused, cudaFuncAttributeMaxDynamicSharedMemorySize, 201216);
        cudaFuncSetAttribute(s2b_fused, cudaFuncAttributeMaxDynamicSharedMemorySize, 174080);
        cudaStreamCreateWithFlags(&sideStream, cudaStreamNonBlocking);
        cudaEventCreateWithFlags(&evPos1, cudaEventDisableTiming);
        cudaEventCreateWithFlags(&evSide, cudaEventDisableTiming);
        attr_done = 1;
    }

    float r2a = (float)(0.1*0.1), r2b = (float)(0.2*0.2);

    // ---- stage 1 (main stream) ----
    fps_kernel<32><<<8, 128, 4096*12 + 64>>>(pts, pos1, 4096, 2048);
    cudaEventRecord(evPos1, 0);

    // ---- side stream: fps16 + radius2 + poscat overlap radius1/s1 ----
    cudaStreamWaitEvent(sideStream, evPos1, 0);
    fps_kernel<16><<<8, 128, 2048*12 + 64, sideStream>>>(pos1, pos2, 2048, 512);
    radius_kernel<<<512, 256, 0, sideStream>>>(pos1, pos2, 2048, 512, r2b, nidx2, cnt2);
    poscat_kernel<<<48, 256, 0, sideStream>>>();
    cudaEventRecord(evSide, sideStream);

    // ---- main stream continues ----
    radius_kernel<<<2048, 256>>>(pts, pos1, 4096, 2048, r2a, nidx1, cnt1);
    s1_fused<<<4096, 256, 89344>>>(pts, s1w1, s1b1, s1w2, s1b2, s1w3, s1b3);
    cudaStreamWaitEvent(0, evSide, 0);
    s2a_fused<<<1024, 256, 201216>>>(s2w1, s2b1, s2w2, s2b2, h2s2);
    s2b_fused<<<1024, 256, 174080>>>(h2s2, s2w3, s2b3);

    // ---- global MLP + pooling + head ----
    gemm_k<<<dim3(4, 32), 256>>>(x2cat, gw1, gb1, g1b, 4096, 256, 259, 1);
    gemm_k<<<dim3(8, 32), 256>>>(g1b, gw2, gb2, g2b, 4096, 512, 256, 1);
    gemm_k<<<dim3(16, 32), 256>>>(g2b, gw3, gb3, g3b, 4096, 1024, 512, 0);
    gmax_kernel<<<dim3(4, 32), 256>>>();
    gemm_k<<<dim3(8, 1), 256>>>(gmx, l1w, l1b, f1, 32, 512, 1024, 1);
    gemm_k<<<dim3(4, 1), 256>>>(f1, l2w, l2b, f2, 32, 256, 512, 1);
    gemm_k<<<dim3(1, 1), 256>>>(f2, l3w, l3b, f3, 32, 7, 256, 0);
    final_kernel<<<1, 64>>>((float*)d_out);
}